// round 3
// baseline (speedup 1.0000x reference)
#include <cuda_runtime.h>
#include <math.h>

#define PI_D 3.14159265358979323846
#define CS 65              // padded stride for smem tables / fields
#define NTHR 264           // 33 * 8

__device__ float gC[33*64];
__device__ float gS[33*64];
__device__ int   g_env_bad;   // 1 if env buffer is int32, 0 if int64

__global__ void init_tables_kernel() {
    int idx = blockIdx.x*blockDim.x + threadIdx.x;
    if (idx == 0) g_env_bad = 0;
    if (idx < 33*64) {
        int k = idx >> 6, n = idx & 63;
        double t = 2.0 * (double)(k*n) / 65.0;
        double s, c;
        sincospi(t, &s, &c);
        gC[idx] = (float)c;
        gS[idx] = (float)s;
    }
}

// If env is really int64, every 8-byte word is in [0,8). If it is int32,
// some 8-byte word will have a nonzero high half (prob ~1 it happens).
__global__ void detect_env_kernel(const long long* __restrict__ env) {
    int i = blockIdx.x*blockDim.x + threadIdx.x;
    if (i < 2048) {
        long long v = env[i];
        if (v < 0 || v >= 8) g_env_bad = 1;
    }
}

__global__ __launch_bounds__(NTHR, 3)
void turb_kernel(const float* __restrict__ y0, const void* __restrict__ envp,
                 const float* __restrict__ params, const float* __restrict__ domain,
                 float* __restrict__ out)
{
    extern __shared__ float sm[];
    float* Csm = sm;               // [33][CS]
    float* Ssm = Csm + 33*CS;      // [33][CS]
    float* xs  = Ssm + 33*CS;      // [64][CS]
    float* bufA = xs + 64*CS;      // 4290 floats (T complex / V complex)
    float* bufB = bufA + 4290;     // 4290 floats (u complex / psi)

    const int tid = threadIdx.x;
    const int b   = blockIdx.x;

    int e;
    if (g_env_bad) e = ((const int*)envp)[b];
    else           e = (int)(((const long long*)envp)[b]);
    const float fdx  = domain[e] * (float)(PI_D / 64.0);
    const float mu   = params[2*e];
    const float fdx2 = fdx * fdx;

    for (int i = tid; i < 33*64; i += NTHR) {
        int k = i >> 6, n = i & 63;
        Csm[k*CS + n] = gC[i];
        Ssm[k*CS + n] = gS[i];
    }
    const float* xin = y0 + (size_t)b * 4096;
    for (int i = tid; i < 4096; i += NTHR)
        xs[(i>>6)*CS + (i & 63)] = xin[i];
    __syncthreads();

    // ---------- Stage 1: T[m][k] = sum_n x[m][n] * G[k][n],  k = 0..32 ----------
    // G[k][n] = C - iS  (n>=1);  G[k][0] = 1 + (C[k][1] + i S[k][1])  (wrap pad)
    {
        float* Tre = bufA;          // [64][33] : m*33 + k
        float* Tim = bufA + 2112;
        const int k  = tid >> 3;    // 0..32
        const int mg = tid & 7;
        float ar[8], ai[8];
        #pragma unroll
        for (int j = 0; j < 8; j++) { ar[j] = 0.f; ai[j] = 0.f; }
        const float* Ck = Csm + k*CS;
        const float* Sk = Ssm + k*CS;
        #pragma unroll 4
        for (int n = 0; n < 64; n++) {
            float c = Ck[n], s = Sk[n];
            #pragma unroll
            for (int j = 0; j < 8; j++) {
                float xv = xs[(mg + 8*j)*CS + n];
                ar[j] += xv * c;
                ai[j] -= xv * s;
            }
        }
        float c1 = Ck[1], s1 = Sk[1];
        #pragma unroll
        for (int j = 0; j < 8; j++) {
            float x0 = xs[(mg + 8*j)*CS];
            ar[j] += x0 * c1;
            ai[j] += x0 * s1;
            Tre[(mg + 8*j)*33 + k] = ar[j];
            Tim[(mg + 8*j)*33 + k] = ai[j];
        }
    }
    __syncthreads();

    // ---------- Stage 2: wf[a][b] = sum_m G[a][m] * T[m][b], a=0..32, b=0..64 ----
    // For b>=33 use T[m][b] = conj(T[m][65-b]).  Then scale by Poisson factor -> u.
    {
        const float* Tre = bufA;
        const float* Tim = bufA + 2112;
        float* ur = bufB;           // [33][CS]
        float* ui = bufB + 2145;
        const int a  = tid >> 3;    // 0..32
        const int bg = tid & 7;
        float wr[9], wi[9], sg[9];
        int col[9], bcolv[9];
        #pragma unroll
        for (int j = 0; j < 9; j++) {
            int bc = bg*9 + j;      // unique cover of 0..71 (>=65 invalid)
            wr[j] = 0.f; wi[j] = 0.f;
            bcolv[j] = bc;
            if (bc <= 32)      { col[j] = bc;      sg[j] =  1.f; }
            else if (bc < 65)  { col[j] = 65 - bc; sg[j] = -1.f; }
            else               { col[j] = 0;       sg[j] =  0.f; }
        }
        const float* Ca = Csm + a*CS;
        const float* Sa = Ssm + a*CS;
        #pragma unroll 2
        for (int m = 0; m < 64; m++) {
            float c = Ca[m], s = Sa[m];
            #pragma unroll
            for (int j = 0; j < 9; j++) {
                float tr = Tre[m*33 + col[j]];
                float ti = sg[j] * Tim[m*33 + col[j]];
                wr[j] += c*tr + s*ti;
                wi[j] += c*ti - s*tr;
            }
        }
        float c1 = Ca[1], s1 = Sa[1];
        const float K2 = (float)((2.0*PI_D/65.0) * (2.0*PI_D/65.0));
        #pragma unroll
        for (int j = 0; j < 9; j++) {
            int bc = bcolv[j];
            if (bc < 65) {
                float tr0 = Tre[col[j]];
                float ti0 = sg[j] * Tim[col[j]];
                float wrr = wr[j] + c1*tr0 - s1*ti0;
                float wii = wi[j] + c1*ti0 + s1*tr0;
                int jb = (bc <= 32) ? bc : bc - 65;
                float c2 = K2 * (float)(a*a + jb*jb);
                float sval = (a == 0 && bc == 0) ? 0.f
                           : 1.0f / ((1e-12f + c2 / fdx2) * 4225.0f);
                ur[a*CS + bc] = wrr * sval;
                ui[a*CS + bc] = wii * sval;
            }
        }
    }
    __syncthreads();

    // ---------- Stage 3: V[a][n] = sum_b u[a][b] * e^{+2πibn/65}, n = 0..63 ------
    {
        const float* ur = bufB;
        const float* ui = bufB + 2145;
        float* Vr = bufA;           // [33][CS]
        float* Vi = bufA + 2145;
        const int a  = tid >> 3;
        const int ng = tid & 7;
        float vr[8], vi[8];
        #pragma unroll
        for (int j = 0; j < 8; j++) { vr[j] = 0.f; vi[j] = 0.f; }
        const float* ua = ur + a*CS;
        const float* va = ui + a*CS;
        #pragma unroll 2
        for (int bq = 0; bq <= 32; bq++) {        // e = C + iS
            float urv = ua[bq], uiv = va[bq];
            const float* Cb = Csm + bq*CS;
            const float* Sb = Ssm + bq*CS;
            #pragma unroll
            for (int j = 0; j < 8; j++) {
                int n = ng + 8*j;
                float c = Cb[n], s = Sb[n];
                vr[j] += urv*c - uiv*s;
                vi[j] += urv*s + uiv*c;
            }
        }
        #pragma unroll 2
        for (int bq = 33; bq < 65; bq++) {        // e = C - iS (conj row)
            float urv = ua[bq], uiv = va[bq];
            const float* Cb = Csm + (65-bq)*CS;
            const float* Sb = Ssm + (65-bq)*CS;
            #pragma unroll
            for (int j = 0; j < 8; j++) {
                int n = ng + 8*j;
                float c = Cb[n], s = Sb[n];
                vr[j] +=  urv*c + uiv*s;
                vi[j] += -urv*s + uiv*c;
            }
        }
        #pragma unroll
        for (int j = 0; j < 8; j++) {
            Vr[a*CS + ng + 8*j] = vr[j];
            Vi[a*CS + ng + 8*j] = vi[j];
        }
    }
    __syncthreads();

    // ---------- Stage 4: psi[m][n] = Vr[0][n] + 2*sum_{a=1..32}(C·Vr - S·Vi) -----
    {
        const float* Vr = bufA;
        const float* Vi = bufA + 2145;
        float* psi = bufB;          // [64][CS]
        if (tid < 256) {
            const int m  = tid & 63;
            const int ng = tid >> 6;   // 0..3
            float acc[16];
            #pragma unroll
            for (int j = 0; j < 16; j++) acc[j] = 0.f;
            #pragma unroll 2
            for (int a = 1; a < 33; a++) {
                float c = Csm[a*CS + m], s = Ssm[a*CS + m];
                #pragma unroll
                for (int j = 0; j < 16; j++) {
                    int n = ng + 4*j;
                    acc[j] += c * Vr[a*CS + n] - s * Vi[a*CS + n];
                }
            }
            #pragma unroll
            for (int j = 0; j < 16; j++) {
                int n = ng + 4*j;
                psi[m*CS + n] = Vr[n] + 2.0f * acc[j];
            }
        }
    }
    __syncthreads();

    // ---------- Stencil: Arakawa Jacobian + laplacian, write dudt ---------------
    {
        const float* psi = bufB;
        float* o = out + (size_t)b * 4096;
        const float inv12 = 1.0f / (12.0f * fdx2);   // (1/(4 fdx2)) / 3
        const float mf    = mu / fdx2;
        for (int idx = tid; idx < 4096; idx += NTHR) {
            int i  = idx >> 6, j = idx & 63;
            int ip = (i+1) & 63, im = (i-1) & 63;
            int jp = (j+1) & 63, jm = (j-1) & 63;
            float Pipj  = psi[ip*CS+j],  Pimj  = psi[im*CS+j];
            float Pijp  = psi[i*CS+jp],  Pijm  = psi[i*CS+jm];
            float Pipjp = psi[ip*CS+jp], Pipjm = psi[ip*CS+jm];
            float Pimjp = psi[im*CS+jp], Pimjm = psi[im*CS+jm];
            float Xc    = xs[i*CS+j];
            float Xipj  = xs[ip*CS+j],   Ximj  = xs[im*CS+j];
            float Xijp  = xs[i*CS+jp],   Xijm  = xs[i*CS+jm];
            float Xipjp = xs[ip*CS+jp],  Xipjm = xs[ip*CS+jm];
            float Ximjp = xs[im*CS+jp],  Ximjm = xs[im*CS+jm];
            float J1 = (Pipj - Pimj)*(Xijp - Xijm) - (Pijp - Pijm)*(Xipj - Ximj);
            float J2 = Xijp*(Pipjp - Pimjp) - Xijm*(Pipjm - Pimjm)
                     - Xipj*(Pipjp - Pipjm) + Ximj*(Pimjp - Pimjm);
            float J3 = Xipjp*(Pipj - Pijp) - Ximjm*(Pijm - Pimj)
                     - Xipjm*(Pipj - Pijm) + Ximjp*(Pijp - Pimj);
            float lap = Ximj + Xijm - 4.0f*Xc + Xijp + Xipjm + Xipj;
            o[idx] = -(J1 + J2 + J3)*inv12 + mf*lap;
        }
    }
}

extern "C" void kernel_launch(void* const* d_in, const int* in_sizes, int n_in,
                              void* d_out, int out_size) {
    // inputs (metadata order): t, y0, env, codes, params, domain
    const float* y0     = (const float*)d_in[1];
    const void*  envp   = d_in[2];
    const float* params = (const float*)d_in[4];
    const float* domain = (const float*)d_in[5];
    float* out = (float*)d_out;

    const int smemBytes = (33*CS*2 + 64*CS + 4290*2) * (int)sizeof(float); // 68120
    cudaFuncSetAttribute(turb_kernel, cudaFuncAttributeMaxDynamicSharedMemorySize, smemBytes);

    init_tables_kernel<<<9, 256>>>();
    detect_env_kernel<<<8, 256>>>((const long long*)envp);
    turb_kernel<<<4096, NTHR, smemBytes>>>(y0, envp, params, domain, out);
}

// round 6
// speedup vs baseline: 1.1889x; 1.1889x over previous
#include <cuda_runtime.h>
#include <math.h>

#define PI_D 3.14159265358979323846
#define CS 65              // padded stride for smem tables / fields
#define NTHR 264           // 33 * 8

typedef unsigned long long u64;

// packed f32x2 helpers (sm_100+ PTX)
#define FMA2(acc, a, b) asm("fma.rn.f32x2 %0, %1, %2, %0;" : "+l"(acc) : "l"(a), "l"(b))
#define PACK2(d, lo, hi) asm("mov.b64 %0, {%1, %2};" : "=l"(d) : "r"(__float_as_uint(lo)), "r"(__float_as_uint(hi)))
#define UNPACK2(lo, hi, s) do { unsigned _l, _h; \
    asm("mov.b64 {%0, %1}, %2;" : "=r"(_l), "=r"(_h) : "l"(s)); \
    lo = __uint_as_float(_l); hi = __uint_as_float(_h); } while (0)

__device__ float2 gCS[33*64];   // (cos, sin)(2*pi*k*n/65)
__device__ int    g_env_bad;    // 1 if env buffer is int32, 0 if int64

__global__ void init_tables_kernel() {
    int idx = blockIdx.x*blockDim.x + threadIdx.x;
    if (idx == 0) g_env_bad = 0;
    if (idx < 33*64) {
        int k = idx >> 6, n = idx & 63;
        double t = 2.0 * (double)(k*n) / 65.0;
        double s, c;
        sincospi(t, &s, &c);
        gCS[idx] = make_float2((float)c, (float)s);
    }
}

__global__ void detect_env_kernel(const long long* __restrict__ env) {
    int i = blockIdx.x*blockDim.x + threadIdx.x;
    if (i < 2048) {
        long long v = env[i];
        if (v < 0 || v >= 8) g_env_bad = 1;
    }
}

__global__ __launch_bounds__(NTHR, 3)
void turb_kernel(const float* __restrict__ y0, const void* __restrict__ envp,
                 const float* __restrict__ params, const float* __restrict__ domain,
                 float* __restrict__ out)
{
    extern __shared__ float smf[];
    float2* cs2  = (float2*)smf;            // [33][CS] packed (c,s): 4290 floats
    float*  xs   = smf + 4290;              // [64][CS] floats: 4160
    float*  bufA = smf + 8450;              // 4290 floats (T2 / V2)
    float*  bufB = smf + 12740;             // 4290 floats (u2 / psi)

    float2* T2 = (float2*)bufA;             // [64][33]
    float2* V2 = (float2*)bufA;             // [33][CS]
    float2* u2 = (float2*)bufB;             // [33][CS]
    float*  psi = bufB;                     // [64][CS]

    const int tid = threadIdx.x;
    const int b   = blockIdx.x;

    int e;
    if (g_env_bad) e = ((const int*)envp)[b];
    else           e = (int)(((const long long*)envp)[b]);
    const float fdx  = domain[e] * (float)(PI_D / 64.0);
    const float mu   = params[2*e];
    const float fdx2 = fdx * fdx;

    for (int i = tid; i < 33*64; i += NTHR) {
        int k = i >> 6, n = i & 63;
        cs2[k*CS + n] = gCS[i];
    }
    const float* xin = y0 + (size_t)b * 4096;
    for (int i = tid; i < 4096; i += NTHR)
        xs[(i>>6)*CS + (i & 63)] = xin[i];
    __syncthreads();

    // ---------- Stage 1: T[m][k] = sum_n x[m][n]*(c - i s) + pad, k=0..32 -------
    // thread = (m, g): m = tid&63, g = tid>>6 in 0..3; k = g + 4j (g==0 also j=8 -> k=32)
    {
        const int m = tid & 63;
        const int g = tid >> 6;
        if (g < 4) {
            u64 P[9];
            #pragma unroll
            for (int j = 0; j < 9; j++) P[j] = 0ULL;
            const float* xrow = xs + m*CS;
            #pragma unroll 2
            for (int n = 0; n < 64; n++) {
                float xv = xrow[n];
                u64 XX; PACK2(XX, xv, xv);
                #pragma unroll
                for (int j = 0; j < 9; j++) {
                    if (j < 8 || g == 0) {
                        int k = g + 4*j;
                        u64 cs = *(const u64*)(cs2 + k*CS + n);
                        FMA2(P[j], XX, cs);
                    }
                }
            }
            float x0 = xrow[0];
            #pragma unroll
            for (int j = 0; j < 9; j++) {
                if (j < 8 || g == 0) {
                    int k = g + 4*j;
                    float2 c1s1 = cs2[k*CS + 1];
                    float ar, asum; UNPACK2(ar, asum, P[j]);
                    T2[m*33 + k] = make_float2(ar + x0*c1s1.x, -asum + x0*c1s1.y);
                }
            }
        }
    }
    __syncthreads();

    // ---------- Stage 2: wf[a][bc] = sum_m (c - i s)(a,m) * T[m][bc]; scale -> u -
    // bc>32 uses T[m][65-bc] conjugated (sign sg). a = tid>>3, bc = (tid&7)*9 + j.
    {
        const int a  = tid >> 3;    // 0..32
        const int bg = tid & 7;
        int col[9]; float sg[9];
        #pragma unroll
        for (int j = 0; j < 9; j++) {
            int bc = bg*9 + j;
            if (bc <= 32)      { col[j] = bc;      sg[j] =  1.f; }
            else if (bc < 65)  { col[j] = 65 - bc; sg[j] = -1.f; }
            else               { col[j] = 0;       sg[j] =  0.f; }
        }
        u64 P[9], Q[9];
        #pragma unroll
        for (int j = 0; j < 9; j++) { P[j] = 0ULL; Q[j] = 0ULL; }
        #pragma unroll 2
        for (int m = 0; m < 64; m++) {
            u64 CSp = *(const u64*)(cs2 + a*CS + m);
            float c, s; UNPACK2(c, s, CSp);
            u64 SCp; PACK2(SCp, s, c);
            const float2* Trow = T2 + m*33;
            #pragma unroll
            for (int j = 0; j < 9; j++) {
                u64 T = *(const u64*)(Trow + col[j]);
                FMA2(P[j], CSp, T);   // (sum c*tr, sum s*ti)
                FMA2(Q[j], SCp, T);   // (sum s*tr, sum c*ti)
            }
        }
        const float2 c1s1 = cs2[a*CS + 1];
        const float K2f = (float)((2.0*PI_D/65.0) * (2.0*PI_D/65.0));
        #pragma unroll
        for (int j = 0; j < 9; j++) {
            int bc = bg*9 + j;
            if (bc < 65) {
                float plo, phi; UNPACK2(plo, phi, P[j]);
                float qlo, qhi; UNPACK2(qlo, qhi, Q[j]);
                float2 T0 = T2[col[j]];            // m = 0 row (pad term)
                float tr0 = T0.x, ti0 = sg[j]*T0.y;
                float wr = plo + sg[j]*phi + c1s1.x*tr0 - c1s1.y*ti0;
                float wi = sg[j]*qhi - qlo + c1s1.x*ti0 + c1s1.y*tr0;
                int jb = (bc <= 32) ? bc : bc - 65;
                float c2 = K2f * (float)(a*a + jb*jb);
                float sval = (a == 0 && bc == 0) ? 0.f
                           : 1.0f / ((1e-12f + c2 / fdx2) * 4225.0f);
                u2[a*CS + bc] = make_float2(wr*sval, wi*sval);
            }
        }
    }
    __syncthreads();

    // ---------- Stage 3: V[a][n] = sum_b u[a][b] * e^{+2πibn/65}, n = 0..63 ------
    {
        const int a  = tid >> 3;
        const int ng = tid & 7;
        u64 P[8], Q[8];
        #pragma unroll
        for (int j = 0; j < 8; j++) { P[j] = 0ULL; Q[j] = 0ULL; }
        const float2* ua = u2 + a*CS;
        for (int bq = 0; bq <= 32; bq++) {        // e = c + i s
            float2 u = ua[bq];
            u64 U1; PACK2(U1, u.x, u.y);          // (ur, ui)
            u64 U2; PACK2(U2, u.y, u.x);          // (ui, ur)
            const float2* csrow = cs2 + bq*CS + ng;
            #pragma unroll
            for (int j = 0; j < 8; j++) {
                u64 cs = *(const u64*)(csrow + 8*j);
                FMA2(P[j], U1, cs);               // (ur*c, ui*s)
                FMA2(Q[j], U2, cs);               // (ui*c, ur*s)
            }
        }
        for (int bq = 33; bq < 65; bq++) {        // e = c - i s (conj row 65-bq)
            float2 u = ua[bq];
            u64 U1; PACK2(U1, u.x, -u.y);         // (ur, -ui)
            u64 U2; PACK2(U2, u.y, -u.x);         // (ui, -ur)
            const float2* csrow = cs2 + (65-bq)*CS + ng;
            #pragma unroll
            for (int j = 0; j < 8; j++) {
                u64 cs = *(const u64*)(csrow + 8*j);
                FMA2(P[j], U1, cs);
                FMA2(Q[j], U2, cs);
            }
        }
        #pragma unroll
        for (int j = 0; j < 8; j++) {
            float plo, phi; UNPACK2(plo, phi, P[j]);
            float qlo, qhi; UNPACK2(qlo, qhi, Q[j]);
            V2[a*CS + ng + 8*j] = make_float2(plo - phi, qlo + qhi);
        }
    }
    __syncthreads();

    // ---------- Stage 4: psi[m][n] = Vr[0][n] + 2*sum_{a=1..32}(c*Vr - s*Vi) -----
    {
        if (tid < 256) {
            const int m  = tid & 63;
            const int ng = tid >> 6;   // 0..3
            u64 P[16];
            #pragma unroll
            for (int j = 0; j < 16; j++) P[j] = 0ULL;
            #pragma unroll 2
            for (int a = 1; a < 33; a++) {
                u64 CSp = *(const u64*)(cs2 + a*CS + m);
                const float2* Vrow = V2 + a*CS + ng;
                #pragma unroll
                for (int j = 0; j < 16; j++) {
                    u64 V = *(const u64*)(Vrow + 4*j);
                    FMA2(P[j], CSp, V);           // (c*Vr, s*Vi)
                }
            }
            #pragma unroll
            for (int j = 0; j < 16; j++) {
                int n = ng + 4*j;
                float plo, phi; UNPACK2(plo, phi, P[j]);
                psi[m*CS + n] = V2[n].x + 2.0f*(plo - phi);
            }
        }
    }
    __syncthreads();

    // ---------- Stencil: Arakawa Jacobian + laplacian, write dudt ---------------
    {
        float* o = out + (size_t)b * 4096;
        const float inv12 = 1.0f / (12.0f * fdx2);   // (1/(4 fdx2)) / 3
        const float mf    = mu / fdx2;
        for (int idx = tid; idx < 4096; idx += NTHR) {
            int i  = idx >> 6, j = idx & 63;
            int ip = (i+1) & 63, im = (i-1) & 63;
            int jp = (j+1) & 63, jm = (j-1) & 63;
            float Pipj  = psi[ip*CS+j],  Pimj  = psi[im*CS+j];
            float Pijp  = psi[i*CS+jp],  Pijm  = psi[i*CS+jm];
            float Pipjp = psi[ip*CS+jp], Pipjm = psi[ip*CS+jm];
            float Pimjp = psi[im*CS+jp], Pimjm = psi[im*CS+jm];
            float Xc    = xs[i*CS+j];
            float Xipj  = xs[ip*CS+j],   Ximj  = xs[im*CS+j];
            float Xijp  = xs[i*CS+jp],   Xijm  = xs[i*CS+jm];
            float Xipjp = xs[ip*CS+jp],  Xipjm = xs[ip*CS+jm];
            float Ximjp = xs[im*CS+jp],  Ximjm = xs[im*CS+jm];
            float J1 = (Pipj - Pimj)*(Xijp - Xijm) - (Pijp - Pijm)*(Xipj - Ximj);
            float J2 = Xijp*(Pipjp - Pimjp) - Xijm*(Pipjm - Pimjm)
                     - Xipj*(Pipjp - Pipjm) + Ximj*(Pimjp - Pimjm);
            float J3 = Xipjp*(Pipj - Pijp) - Ximjm*(Pijm - Pimj)
                     - Xipjm*(Pipj - Pijm) + Ximjp*(Pijp - Pimj);
            float lap = Ximj + Xijm - 4.0f*Xc + Xijp + Xipjm + Xipj;
            o[idx] = -(J1 + J2 + J3)*inv12 + mf*lap;
        }
    }
}

extern "C" void kernel_launch(void* const* d_in, const int* in_sizes, int n_in,
                              void* d_out, int out_size) {
    // inputs (metadata order): t, y0, env, codes, params, domain
    const float* y0     = (const float*)d_in[1];
    const void*  envp   = d_in[2];
    const float* params = (const float*)d_in[4];
    const float* domain = (const float*)d_in[5];
    float* out = (float*)d_out;

    const int smemBytes = 17030 * (int)sizeof(float); // 68120 B
    cudaFuncSetAttribute(turb_kernel, cudaFuncAttributeMaxDynamicSharedMemorySize, smemBytes);

    init_tables_kernel<<<9, 256>>>();
    detect_env_kernel<<<8, 256>>>((const long long*)envp);
    turb_kernel<<<4096, NTHR, smemBytes>>>(y0, envp, params, domain, out);
}

// round 10
// speedup vs baseline: 1.7263x; 1.4520x over previous
#include <cuda_runtime.h>
#include <math.h>

#define PI_D 3.14159265358979323846
#define CS 65              // padded stride for smem tables / fields
#define NTHR 264

typedef unsigned long long u64;

// packed f32x2 helpers (sm_100+ PTX)
#define FMA2(acc, a, b) asm("fma.rn.f32x2 %0, %1, %2, %0;" : "+l"(acc) : "l"(a), "l"(b))
#define PACK2(d, lo, hi) asm("mov.b64 %0, {%1, %2};" : "=l"(d) : "r"(__float_as_uint(lo)), "r"(__float_as_uint(hi)))
#define UNPACK2(lo, hi, s) do { unsigned _l, _h; \
    asm("mov.b64 {%0, %1}, %2;" : "=r"(_l), "=r"(_h) : "l"(s)); \
    lo = __uint_as_float(_l); hi = __uint_as_float(_h); } while (0)

__device__ float2 gCS[33*64];   // (cos, sin)(2*pi*k*n/65)
__device__ int    g_env_bad;    // 1 if env buffer is int32, 0 if int64

__global__ void init_tables_kernel() {
    int idx = blockIdx.x*blockDim.x + threadIdx.x;
    if (idx == 0) g_env_bad = 0;
    if (idx < 33*64) {
        int k = idx >> 6, n = idx & 63;
        double t = 2.0 * (double)(k*n) / 65.0;
        double s, c;
        sincospi(t, &s, &c);
        gCS[idx] = make_float2((float)c, (float)s);
    }
}

__global__ void detect_env_kernel(const long long* __restrict__ env) {
    int i = blockIdx.x*blockDim.x + threadIdx.x;
    if (i < 2048) {
        long long v = env[i];
        if (v < 0 || v >= 8) g_env_bad = 1;
    }
}

__global__ __launch_bounds__(NTHR, 3)
void turb_kernel(const float* __restrict__ y0, const void* __restrict__ envp,
                 const float* __restrict__ params, const float* __restrict__ domain,
                 float* __restrict__ out)
{
    extern __shared__ float smf[];
    float2* cs2  = (float2*)smf;            // [33][CS] packed (c,s): 4290 floats
    float*  xs   = smf + 4290;              // [64][CS] floats: 4160
    float*  bufA = smf + 8450;              // 4290 floats (T2 / V2)
    float*  bufB = smf + 12740;             // 4290 floats (u2 / psi)

    float2* T2 = (float2*)bufA;             // [64][33]
    float2* V2 = (float2*)bufA;             // [33][CS]
    float2* u2 = (float2*)bufB;             // [33][CS]
    float*  psi = bufB;                     // [64][CS]

    const int tid = threadIdx.x;
    const int b   = blockIdx.x;

    int e;
    if (g_env_bad) e = ((const int*)envp)[b];
    else           e = (int)(((const long long*)envp)[b]);
    const float fdx  = domain[e] * (float)(PI_D / 64.0);
    const float mu   = params[2*e];
    const float fdx2 = fdx * fdx;

    for (int i = tid; i < 33*64; i += NTHR) {
        int k = i >> 6, n = i & 63;
        cs2[k*CS + n] = gCS[i];
    }
    const float* xin = y0 + (size_t)b * 4096;
    for (int i = tid; i < 4096; i += NTHR)
        xs[(i>>6)*CS + (i & 63)] = xin[i];
    __syncthreads();

    // ---------- Stage 1: T[m][k] = sum_n x[m][n]*(c - i s) + pad, k=0..32 -------
    // Tile: thread = (mg 0..31, kg 0..6); m in {mg, mg+32}, k = kg*5 + jj (k<33).
    {
        const int mg = tid & 31;
        const int kg = tid >> 5;
        if (kg < 7) {
            u64 P0[5], P1[5];
            #pragma unroll
            for (int j = 0; j < 5; j++) { P0[j] = 0ULL; P1[j] = 0ULL; }
            const float* xr0 = xs + mg*CS;
            const float* xr1 = xs + (mg+32)*CS;
            #pragma unroll 2
            for (int n = 0; n < 64; n++) {
                float x0v = xr0[n], x1v = xr1[n];
                u64 X0; PACK2(X0, x0v, x0v);
                u64 X1; PACK2(X1, x1v, x1v);
                #pragma unroll
                for (int jj = 0; jj < 5; jj++) {
                    int k = kg*5 + jj;
                    if (k < 33) {
                        u64 cs = *(const u64*)(cs2 + k*CS + n);
                        FMA2(P0[jj], X0, cs);   // (sum x*c, sum x*s)
                        FMA2(P1[jj], X1, cs);
                    }
                }
            }
            float x00 = xr0[0], x10 = xr1[0];
            #pragma unroll
            for (int jj = 0; jj < 5; jj++) {
                int k = kg*5 + jj;
                if (k < 33) {
                    float2 c1s1 = cs2[k*CS + 1];
                    float ar, as; UNPACK2(ar, as, P0[jj]);
                    T2[mg*33 + k] = make_float2(ar + x00*c1s1.x, -as + x00*c1s1.y);
                    UNPACK2(ar, as, P1[jj]);
                    T2[(mg+32)*33 + k] = make_float2(ar + x10*c1s1.x, -as + x10*c1s1.y);
                }
            }
        }
    }
    __syncthreads();

    // ---------- Stage 2: wf[a][bc] = sum_m (c - i s)(a,m) * T[m][bc]; scale -> u -
    // Tile: thread = (bcg 0..12, apg 0..16); a in {2apg, 2apg+1}, bc = bcg*5+jj.
    {
        const int bcg = tid % 13;
        const int apg = tid / 13;
        if (apg < 17) {
            const int a0 = 2*apg;
            const bool hasA1 = (a0 + 1 <= 32);
            const int a1 = hasA1 ? a0 + 1 : 32;
            int col[5]; float sg[5];
            #pragma unroll
            for (int jj = 0; jj < 5; jj++) {
                int bc = bcg*5 + jj;            // 0..64, all valid
                if (bc <= 32) { col[jj] = bc;      sg[jj] =  1.f; }
                else          { col[jj] = 65 - bc; sg[jj] = -1.f; }
            }
            u64 P0[5], Q0[5], P1[5], Q1[5];
            #pragma unroll
            for (int jj = 0; jj < 5; jj++) { P0[jj]=0ULL; Q0[jj]=0ULL; P1[jj]=0ULL; Q1[jj]=0ULL; }
            #pragma unroll 2
            for (int m = 0; m < 64; m++) {
                u64 CS0 = *(const u64*)(cs2 + a0*CS + m);
                u64 CS1 = *(const u64*)(cs2 + a1*CS + m);
                float c0, s0; UNPACK2(c0, s0, CS0);
                float c1, s1; UNPACK2(c1, s1, CS1);
                u64 SC0; PACK2(SC0, s0, c0);
                u64 SC1; PACK2(SC1, s1, c1);
                const float2* Trow = T2 + m*33;
                #pragma unroll
                for (int jj = 0; jj < 5; jj++) {
                    u64 T = *(const u64*)(Trow + col[jj]);
                    FMA2(P0[jj], CS0, T);   // (sum c*tr, sum s*ti)
                    FMA2(Q0[jj], SC0, T);   // (sum s*tr, sum c*ti)
                    FMA2(P1[jj], CS1, T);
                    FMA2(Q1[jj], SC1, T);
                }
            }
            const float K2f = (float)((2.0*PI_D/65.0) * (2.0*PI_D/65.0));
            const float2 cp0 = cs2[a0*CS + 1];
            const float2 cp1 = cs2[a1*CS + 1];
            #pragma unroll
            for (int jj = 0; jj < 5; jj++) {
                int bc = bcg*5 + jj;
                float2 T0 = T2[col[jj]];            // m = 0 row (pad term)
                float tr0 = T0.x, ti0 = sg[jj]*T0.y;
                int jb = (bc <= 32) ? bc : bc - 65;
                float jb2 = (float)(jb*jb);
                {
                    float plo, phi; UNPACK2(plo, phi, P0[jj]);
                    float qlo, qhi; UNPACK2(qlo, qhi, Q0[jj]);
                    float wr = plo + sg[jj]*phi + cp0.x*tr0 - cp0.y*ti0;
                    float wi = sg[jj]*qhi - qlo + cp0.x*ti0 + cp0.y*tr0;
                    float c2 = K2f * ((float)(a0*a0) + jb2);
                    float sval = (a0 == 0 && bc == 0) ? 0.f
                               : 1.0f / ((1e-12f + c2 / fdx2) * 4225.0f);
                    u2[a0*CS + bc] = make_float2(wr*sval, wi*sval);
                }
                if (hasA1) {
                    float plo, phi; UNPACK2(plo, phi, P1[jj]);
                    float qlo, qhi; UNPACK2(qlo, qhi, Q1[jj]);
                    float wr = plo + sg[jj]*phi + cp1.x*tr0 - cp1.y*ti0;
                    float wi = sg[jj]*qhi - qlo + cp1.x*ti0 + cp1.y*tr0;
                    float c2 = K2f * ((float)(a1*a1) + jb2);
                    float sval = 1.0f / ((1e-12f + c2 / fdx2) * 4225.0f);
                    u2[a1*CS + bc] = make_float2(wr*sval, wi*sval);
                }
            }
        }
    }
    __syncthreads();

    // ---------- Stage 3: V[a][n] = sum_b u[a][b] * e^{+2πibn/65}, n = 0..63 ------
    // Tile: thread = (ngrp 0..12, apg 0..16); a in {2apg, 2apg+1}, n = ngrp*5+jj (<64).
    {
        const int ngrp = tid % 13;
        const int apg  = tid / 13;
        if (apg < 17) {
            const int a0 = 2*apg;
            const bool hasA1 = (a0 + 1 <= 32);
            const int a1 = hasA1 ? a0 + 1 : 32;
            u64 P0[5], Q0[5], P1[5], Q1[5];
            #pragma unroll
            for (int jj = 0; jj < 5; jj++) { P0[jj]=0ULL; Q0[jj]=0ULL; P1[jj]=0ULL; Q1[jj]=0ULL; }
            const float2* ua0 = u2 + a0*CS;
            const float2* ua1 = u2 + a1*CS;
            for (int bq = 0; bq <= 32; bq++) {        // e = c + i s
                float2 u0 = ua0[bq], u1 = ua1[bq];
                u64 U10; PACK2(U10, u0.x, u0.y);
                u64 U20; PACK2(U20, u0.y, u0.x);
                u64 U11; PACK2(U11, u1.x, u1.y);
                u64 U21; PACK2(U21, u1.y, u1.x);
                const float2* csrow = cs2 + bq*CS + ngrp*5;
                #pragma unroll
                for (int jj = 0; jj < 5; jj++) {
                    u64 cs = *(const u64*)(csrow + jj);
                    FMA2(P0[jj], U10, cs);            // (ur*c, ui*s)
                    FMA2(Q0[jj], U20, cs);            // (ui*c, ur*s)
                    FMA2(P1[jj], U11, cs);
                    FMA2(Q1[jj], U21, cs);
                }
            }
            for (int bq = 33; bq < 65; bq++) {        // e = c - i s (conj row 65-bq)
                float2 u0 = ua0[bq], u1 = ua1[bq];
                u64 U10; PACK2(U10, u0.x, -u0.y);
                u64 U20; PACK2(U20, u0.y, -u0.x);
                u64 U11; PACK2(U11, u1.x, -u1.y);
                u64 U21; PACK2(U21, u1.y, -u1.x);
                const float2* csrow = cs2 + (65-bq)*CS + ngrp*5;
                #pragma unroll
                for (int jj = 0; jj < 5; jj++) {
                    u64 cs = *(const u64*)(csrow + jj);
                    FMA2(P0[jj], U10, cs);
                    FMA2(Q0[jj], U20, cs);
                    FMA2(P1[jj], U11, cs);
                    FMA2(Q1[jj], U21, cs);
                }
            }
            #pragma unroll
            for (int jj = 0; jj < 5; jj++) {
                int n = ngrp*5 + jj;
                if (n < 64) {
                    float plo, phi; UNPACK2(plo, phi, P0[jj]);
                    float qlo, qhi; UNPACK2(qlo, qhi, Q0[jj]);
                    V2[a0*CS + n] = make_float2(plo - phi, qlo + qhi);
                    if (hasA1) {
                        UNPACK2(plo, phi, P1[jj]);
                        UNPACK2(qlo, qhi, Q1[jj]);
                        V2[a1*CS + n] = make_float2(plo - phi, qlo + qhi);
                    }
                }
            }
        }
    }
    __syncthreads();

    // ---------- Stage 4: psi[m][n] = Vr[0][n] + 2*sum_{a=1..32}(c*Vr - s*Vi) -----
    // Tile: thread = (mg 0..31, ngg 0..7); m in {mg, mg+32}, n = ngg + 8*j.
    {
        if (tid < 256) {
            const int mg  = tid & 31;
            const int ngg = tid >> 5;   // 0..7
            u64 P0[8], P1[8];
            #pragma unroll
            for (int j = 0; j < 8; j++) { P0[j] = 0ULL; P1[j] = 0ULL; }
            #pragma unroll 2
            for (int a = 1; a < 33; a++) {
                u64 C0 = *(const u64*)(cs2 + a*CS + mg);
                u64 C1 = *(const u64*)(cs2 + a*CS + mg + 32);
                const float2* Vrow = V2 + a*CS + ngg;
                #pragma unroll
                for (int j = 0; j < 8; j++) {
                    u64 V = *(const u64*)(Vrow + 8*j);
                    FMA2(P0[j], C0, V);           // (c*Vr, s*Vi)
                    FMA2(P1[j], C1, V);
                }
            }
            #pragma unroll
            for (int j = 0; j < 8; j++) {
                int n = ngg + 8*j;
                float v0r = V2[n].x;
                float plo, phi; UNPACK2(plo, phi, P0[j]);
                psi[mg*CS + n] = v0r + 2.0f*(plo - phi);
                UNPACK2(plo, phi, P1[j]);
                psi[(mg+32)*CS + n] = v0r + 2.0f*(plo - phi);
            }
        }
    }
    __syncthreads();

    // ---------- Stencil: Arakawa Jacobian + laplacian, write dudt ---------------
    {
        float* o = out + (size_t)b * 4096;
        const float inv12 = 1.0f / (12.0f * fdx2);   // (1/(4 fdx2)) / 3
        const float mf    = mu / fdx2;
        for (int idx = tid; idx < 4096; idx += NTHR) {
            int i  = idx >> 6, j = idx & 63;
            int ip = (i+1) & 63, im = (i-1) & 63;
            int jp = (j+1) & 63, jm = (j-1) & 63;
            float Pipj  = psi[ip*CS+j],  Pimj  = psi[im*CS+j];
            float Pijp  = psi[i*CS+jp],  Pijm  = psi[i*CS+jm];
            float Pipjp = psi[ip*CS+jp], Pipjm = psi[ip*CS+jm];
            float Pimjp = psi[im*CS+jp], Pimjm = psi[im*CS+jm];
            float Xc    = xs[i*CS+j];
            float Xipj  = xs[ip*CS+j],   Ximj  = xs[im*CS+j];
            float Xijp  = xs[i*CS+jp],   Xijm  = xs[i*CS+jm];
            float Xipjp = xs[ip*CS+jp],  Xipjm = xs[ip*CS+jm];
            float Ximjp = xs[im*CS+jp],  Ximjm = xs[im*CS+jm];
            float J1 = (Pipj - Pimj)*(Xijp - Xijm) - (Pijp - Pijm)*(Xipj - Ximj);
            float J2 = Xijp*(Pipjp - Pimjp) - Xijm*(Pipjm - Pimjm)
                     - Xipj*(Pipjp - Pipjm) + Ximj*(Pimjp - Pimjm);
            float J3 = Xipjp*(Pipj - Pijp) - Ximjm*(Pijm - Pimj)
                     - Xipjm*(Pipj - Pijm) + Ximjp*(Pijp - Pimj);
            float lap = Ximj + Xijm - 4.0f*Xc + Xijp + Xipjm + Xipj;
            o[idx] = -(J1 + J2 + J3)*inv12 + mf*lap;
        }
    }
}

extern "C" void kernel_launch(void* const* d_in, const int* in_sizes, int n_in,
                              void* d_out, int out_size) {
    // inputs (metadata order): t, y0, env, codes, params, domain
    const float* y0     = (const float*)d_in[1];
    const void*  envp   = d_in[2];
    const float* params = (const float*)d_in[4];
    const float* domain = (const float*)d_in[5];
    float* out = (float*)d_out;

    const int smemBytes = 17030 * (int)sizeof(float); // 68120 B
    cudaFuncSetAttribute(turb_kernel, cudaFuncAttributeMaxDynamicSharedMemorySize, smemBytes);

    init_tables_kernel<<<9, 256>>>();
    detect_env_kernel<<<8, 256>>>((const long long*)envp);
    turb_kernel<<<4096, NTHR, smemBytes>>>(y0, envp, params, domain, out);
}

// round 12
// speedup vs baseline: 2.1853x; 1.2659x over previous
#include <cuda_runtime.h>
#include <math.h>

#define PI_D 3.14159265358979323846
#define CS 65              // padded stride for smem tables / fields
#define NTHR 256

typedef unsigned long long u64;

// packed f32x2 helpers (sm_100+ PTX)
#define FMA2(acc, a, b) asm("fma.rn.f32x2 %0, %1, %2, %0;" : "+l"(acc) : "l"(a), "l"(b))
#define PACK2(d, lo, hi) asm("mov.b64 %0, {%1, %2};" : "=l"(d) : "r"(__float_as_uint(lo)), "r"(__float_as_uint(hi)))
#define UNPACK2(lo, hi, s) do { unsigned _l, _h; \
    asm("mov.b64 {%0, %1}, %2;" : "=r"(_l), "=r"(_h) : "l"(s)); \
    lo = __uint_as_float(_l); hi = __uint_as_float(_h); } while (0)

__device__ float2 gCS[33*64];   // (cos, sin)(2*pi*k*n/65)
__device__ int    g_env_bad;    // 1 if env buffer is int32, 0 if int64

__global__ void init_tables_kernel() {
    int idx = blockIdx.x*blockDim.x + threadIdx.x;
    if (idx == 0) g_env_bad = 0;
    if (idx < 33*64) {
        int k = idx >> 6, n = idx & 63;
        double t = 2.0 * (double)(k*n) / 65.0;
        double s, c;
        sincospi(t, &s, &c);
        gCS[idx] = make_float2((float)c, (float)s);
    }
}

__global__ void detect_env_kernel(const long long* __restrict__ env) {
    int i = blockIdx.x*blockDim.x + threadIdx.x;
    if (i < 2048) {
        long long v = env[i];
        if (v < 0 || v >= 8) g_env_bad = 1;
    }
}

__global__ __launch_bounds__(NTHR, 3)
void turb_kernel(const float* __restrict__ y0, const void* __restrict__ envp,
                 const float* __restrict__ params, const float* __restrict__ domain,
                 float* __restrict__ out)
{
    extern __shared__ float smf[];
    float2* cs2  = (float2*)smf;            // [33][CS] packed (c,s): 4290 floats
    float*  xs   = smf + 4290;              // [64][CS] floats: 4160
    float*  bufA = smf + 8450;              // 4290 floats (T2 / V2)
    float*  bufB = smf + 12740;             // 4290 floats (u2 / psi)

    float2* T2 = (float2*)bufA;             // [64][33]
    float2* V2 = (float2*)bufA;             // [33][CS]
    float2* u2 = (float2*)bufB;             // [33][CS]
    float*  psi = bufB;                     // [64][CS]

    const int tid = threadIdx.x;
    const int b   = blockIdx.x;

    int e;
    if (g_env_bad) e = ((const int*)envp)[b];
    else           e = (int)(((const long long*)envp)[b]);
    const float fdx  = domain[e] * (float)(PI_D / 64.0);
    const float mu   = params[2*e];
    const float fdx2 = fdx * fdx;

    for (int i = tid; i < 33*64; i += NTHR) {
        int k = i >> 6, n = i & 63;
        cs2[k*CS + n] = gCS[i];
    }
    const float* xin = y0 + (size_t)b * 4096;
    for (int i = tid; i < 4096; i += NTHR)
        xs[(i>>6)*CS + (i & 63)] = xin[i];
    __syncthreads();

    // ---------- Stage 1: T[m][k] = sum_{n=0..64} xpad[m][n]*(c - i s), k=0..32 --
    // Conjugate-pair fold over (n, 65-n), n=1..32 (xpad[64]=x[0]); n=0 single.
    // contribution = c*A - i*s*B, A=x1+x2, B=x1-x2. P=(sum c*A, sum s*B).
    // Tile: thread = (mg 0..31, kg 0..7); m in {mg,mg+32}, k = kg+8*jj (k<=32).
    {
        const int mg = tid & 31;
        const int kg = tid >> 5;
        u64 P0[5], P1[5];
        #pragma unroll
        for (int j = 0; j < 5; j++) { P0[j] = 0ULL; P1[j] = 0ULL; }
        const float* xr0 = xs + mg*CS;
        const float* xr1 = xs + (mg+32)*CS;
        #pragma unroll 2
        for (int n = 1; n <= 32; n++) {
            int n2 = (65 - n) & 63;          // 64 -> 0 (pad wrap), else 65-n
            float x10 = xr0[n], x20 = xr0[n2];
            float x11 = xr1[n], x21 = xr1[n2];
            u64 AB0; PACK2(AB0, x10 + x20, x10 - x20);
            u64 AB1; PACK2(AB1, x11 + x21, x11 - x21);
            #pragma unroll
            for (int jj = 0; jj < 5; jj++) {
                if (jj < 4 || kg == 0) {
                    int k = kg + 8*jj;
                    u64 cs = *(const u64*)(cs2 + k*CS + n);
                    FMA2(P0[jj], AB0, cs);   // (sum c*A, sum s*B)
                    FMA2(P1[jj], AB1, cs);
                }
            }
        }
        float x00 = xr0[0], x01 = xr1[0];    // n=0 single: +(x0, 0)
        #pragma unroll
        for (int jj = 0; jj < 5; jj++) {
            if (jj < 4 || kg == 0) {
                int k = kg + 8*jj;
                float plo, phi; UNPACK2(plo, phi, P0[jj]);
                T2[mg*33 + k] = make_float2(plo + x00, -phi);
                UNPACK2(plo, phi, P1[jj]);
                T2[(mg+32)*33 + k] = make_float2(plo + x01, -phi);
            }
        }
    }
    __syncthreads();

    // ---------- Stage 2: wf[a][bc] = sum_m (c - i s)(a,m) * T[m][bc]; scale -> u -
    // Tile: thread = (apg 0..16, bcg 0..14); a in {2apg, 2apg+1}, bc = bcg + 15*jj.
    {
        const int bcg = tid % 15;
        const int apg = tid / 15;
        if (apg < 17) {
            const int a0 = 2*apg;
            const bool hasA1 = (a0 + 1 <= 32);
            const int a1 = hasA1 ? a0 + 1 : 32;
            int col[5]; float sg[5]; bool val[5];
            #pragma unroll
            for (int jj = 0; jj < 5; jj++) {
                int bc = bcg + 15*jj;
                val[jj] = (bc < 65);
                int bcc = val[jj] ? bc : 0;
                if (bcc <= 32) { col[jj] = bcc;      sg[jj] =  1.f; }
                else           { col[jj] = 65 - bcc; sg[jj] = -1.f; }
            }
            u64 P0[5], Q0[5], P1[5], Q1[5];
            #pragma unroll
            for (int jj = 0; jj < 5; jj++) { P0[jj]=0ULL; Q0[jj]=0ULL; P1[jj]=0ULL; Q1[jj]=0ULL; }
            #pragma unroll 2
            for (int m = 0; m < 64; m++) {
                u64 CS0 = *(const u64*)(cs2 + a0*CS + m);
                u64 CS1 = *(const u64*)(cs2 + a1*CS + m);
                float c0, s0; UNPACK2(c0, s0, CS0);
                float c1, s1; UNPACK2(c1, s1, CS1);
                u64 SC0; PACK2(SC0, s0, c0);
                u64 SC1; PACK2(SC1, s1, c1);
                const float2* Trow = T2 + m*33;
                #pragma unroll
                for (int jj = 0; jj < 5; jj++) {
                    u64 T = *(const u64*)(Trow + col[jj]);
                    FMA2(P0[jj], CS0, T);   // (sum c*tr, sum s*ti)
                    FMA2(Q0[jj], SC0, T);   // (sum s*tr, sum c*ti)
                    FMA2(P1[jj], CS1, T);
                    FMA2(Q1[jj], SC1, T);
                }
            }
            const float K2f = (float)((2.0*PI_D/65.0) * (2.0*PI_D/65.0));
            const float2 cp0 = cs2[a0*CS + 1];
            const float2 cp1 = cs2[a1*CS + 1];
            #pragma unroll
            for (int jj = 0; jj < 5; jj++) {
                if (val[jj]) {
                    int bc = bcg + 15*jj;
                    float2 T0 = T2[col[jj]];            // m = 0 row (pad term)
                    float tr0 = T0.x, ti0 = sg[jj]*T0.y;
                    int jb = (bc <= 32) ? bc : bc - 65;
                    float jb2 = (float)(jb*jb);
                    {
                        float plo, phi; UNPACK2(plo, phi, P0[jj]);
                        float qlo, qhi; UNPACK2(qlo, qhi, Q0[jj]);
                        float wr = plo + sg[jj]*phi + cp0.x*tr0 - cp0.y*ti0;
                        float wi = sg[jj]*qhi - qlo + cp0.x*ti0 + cp0.y*tr0;
                        float c2 = K2f * ((float)(a0*a0) + jb2);
                        float sval = (a0 == 0 && bc == 0) ? 0.f
                                   : 1.0f / ((1e-12f + c2 / fdx2) * 4225.0f);
                        u2[a0*CS + bc] = make_float2(wr*sval, wi*sval);
                    }
                    if (hasA1) {
                        float plo, phi; UNPACK2(plo, phi, P1[jj]);
                        float qlo, qhi; UNPACK2(qlo, qhi, Q1[jj]);
                        float wr = plo + sg[jj]*phi + cp1.x*tr0 - cp1.y*ti0;
                        float wi = sg[jj]*qhi - qlo + cp1.x*ti0 + cp1.y*tr0;
                        float c2 = K2f * ((float)(a1*a1) + jb2);
                        float sval = 1.0f / ((1e-12f + c2 / fdx2) * 4225.0f);
                        u2[a1*CS + bc] = make_float2(wr*sval, wi*sval);
                    }
                }
            }
        }
    }
    __syncthreads();

    // ---------- Stage 3: V[a][n] = sum_{b=0..64} u[a][b] * e^{+2πibn/65} --------
    // Conjugate-pair fold over (b, 65-b), b=1..32; b=0 single.
    // contribution = c*A + i*s*B: re = c*Ar - s*Bi, im = c*Ai + s*Br.
    // P=(sum c*Ar, sum s*Bi) via FMA2(P,(Ar,Bi),cs); Q=(sum c*Ai, sum s*Br).
    // Tile: thread = (apg 0..16, ngrp 0..12); a in {2apg, 2apg+1}, n = ngrp*5+jj.
    {
        const int ngrp = tid % 13;
        const int apg  = tid / 13;
        if (apg < 17) {
            const int a0 = 2*apg;
            const bool hasA1 = (a0 + 1 <= 32);
            const int a1 = hasA1 ? a0 + 1 : 32;
            u64 P0[5], Q0[5], P1[5], Q1[5];
            #pragma unroll
            for (int jj = 0; jj < 5; jj++) { P0[jj]=0ULL; Q0[jj]=0ULL; P1[jj]=0ULL; Q1[jj]=0ULL; }
            const float2* ua0 = u2 + a0*CS;
            const float2* ua1 = u2 + a1*CS;
            #pragma unroll 2
            for (int bq = 1; bq <= 32; bq++) {
                float2 p0 = ua0[bq], q0 = ua0[65-bq];
                float2 p1 = ua1[bq], q1 = ua1[65-bq];
                u64 A0; PACK2(A0, p0.x + q0.x, p0.y - q0.y);   // (Ar, Bi)
                u64 B0; PACK2(B0, p0.y + q0.y, p0.x - q0.x);   // (Ai, Br)
                u64 A1; PACK2(A1, p1.x + q1.x, p1.y - q1.y);
                u64 B1; PACK2(B1, p1.y + q1.y, p1.x - q1.x);
                const float2* csrow = cs2 + bq*CS + ngrp*5;
                #pragma unroll
                for (int jj = 0; jj < 5; jj++) {
                    u64 cs = *(const u64*)(csrow + jj);
                    FMA2(P0[jj], A0, cs);
                    FMA2(Q0[jj], B0, cs);
                    FMA2(P1[jj], A1, cs);
                    FMA2(Q1[jj], B1, cs);
                }
            }
            float2 u00 = ua0[0], u01 = ua1[0];   // b=0 single
            #pragma unroll
            for (int jj = 0; jj < 5; jj++) {
                int n = ngrp*5 + jj;
                if (n < 64) {
                    float plo, phi; UNPACK2(plo, phi, P0[jj]);
                    float qlo, qhi; UNPACK2(qlo, qhi, Q0[jj]);
                    V2[a0*CS + n] = make_float2(plo - phi + u00.x, qlo + qhi + u00.y);
                    if (hasA1) {
                        UNPACK2(plo, phi, P1[jj]);
                        UNPACK2(qlo, qhi, Q1[jj]);
                        V2[a1*CS + n] = make_float2(plo - phi + u01.x, qlo + qhi + u01.y);
                    }
                }
            }
        }
    }
    __syncthreads();

    // ---------- Stage 4: psi[m][n] = Vr[0][n] + 2*sum_{a=1..32}(c*Vr - s*Vi) -----
    // Tile: thread = (mg 0..31, ngg 0..7); m in {mg, mg+32}, n = ngg + 8*j.
    {
        const int mg  = tid & 31;
        const int ngg = tid >> 5;   // 0..7
        u64 P0[8], P1[8];
        #pragma unroll
        for (int j = 0; j < 8; j++) { P0[j] = 0ULL; P1[j] = 0ULL; }
        #pragma unroll 2
        for (int a = 1; a < 33; a++) {
            u64 C0 = *(const u64*)(cs2 + a*CS + mg);
            u64 C1 = *(const u64*)(cs2 + a*CS + mg + 32);
            const float2* Vrow = V2 + a*CS + ngg;
            #pragma unroll
            for (int j = 0; j < 8; j++) {
                u64 V = *(const u64*)(Vrow + 8*j);
                FMA2(P0[j], C0, V);           // (c*Vr, s*Vi)
                FMA2(P1[j], C1, V);
            }
        }
        #pragma unroll
        for (int j = 0; j < 8; j++) {
            int n = ngg + 8*j;
            float v0r = V2[n].x;
            float plo, phi; UNPACK2(plo, phi, P0[j]);
            psi[mg*CS + n] = v0r + 2.0f*(plo - phi);
            UNPACK2(plo, phi, P1[j]);
            psi[(mg+32)*CS + n] = v0r + 2.0f*(plo - phi);
        }
    }
    __syncthreads();

    // ---------- Stencil: Arakawa Jacobian + laplacian, write dudt ---------------
    {
        float* o = out + (size_t)b * 4096;
        const float inv12 = 1.0f / (12.0f * fdx2);   // (1/(4 fdx2)) / 3
        const float mf    = mu / fdx2;
        #pragma unroll 2
        for (int idx = tid; idx < 4096; idx += NTHR) {
            int i  = idx >> 6, j = idx & 63;
            int ip = (i+1) & 63, im = (i-1) & 63;
            int jp = (j+1) & 63, jm = (j-1) & 63;
            float Pipj  = psi[ip*CS+j],  Pimj  = psi[im*CS+j];
            float Pijp  = psi[i*CS+jp],  Pijm  = psi[i*CS+jm];
            float Pipjp = psi[ip*CS+jp], Pipjm = psi[ip*CS+jm];
            float Pimjp = psi[im*CS+jp], Pimjm = psi[im*CS+jm];
            float Xc    = xs[i*CS+j];
            float Xipj  = xs[ip*CS+j],   Ximj  = xs[im*CS+j];
            float Xijp  = xs[i*CS+jp],   Xijm  = xs[i*CS+jm];
            float Xipjp = xs[ip*CS+jp],  Xipjm = xs[ip*CS+jm];
            float Ximjp = xs[im*CS+jp],  Ximjm = xs[im*CS+jm];
            float J1 = (Pipj - Pimj)*(Xijp - Xijm) - (Pijp - Pijm)*(Xipj - Ximj);
            float J2 = Xijp*(Pipjp - Pimjp) - Xijm*(Pipjm - Pimjm)
                     - Xipj*(Pipjp - Pipjm) + Ximj*(Pimjp - Pimjm);
            float J3 = Xipjp*(Pipj - Pijp) - Ximjm*(Pijm - Pimj)
                     - Xipjm*(Pipj - Pijm) + Ximjp*(Pijp - Pimj);
            float lap = Ximj + Xijm - 4.0f*Xc + Xijp + Xipjm + Xipj;
            o[idx] = -(J1 + J2 + J3)*inv12 + mf*lap;
        }
    }
}

extern "C" void kernel_launch(void* const* d_in, const int* in_sizes, int n_in,
                              void* d_out, int out_size) {
    // inputs (metadata order): t, y0, env, codes, params, domain
    const float* y0     = (const float*)d_in[1];
    const void*  envp   = d_in[2];
    const float* params = (const float*)d_in[4];
    const float* domain = (const float*)d_in[5];
    float* out = (float*)d_out;

    const int smemBytes = 17030 * (int)sizeof(float); // 68120 B
    cudaFuncSetAttribute(turb_kernel, cudaFuncAttributeMaxDynamicSharedMemorySize, smemBytes);

    init_tables_kernel<<<9, 256>>>();
    detect_env_kernel<<<8, 256>>>((const long long*)envp);
    turb_kernel<<<4096, NTHR, smemBytes>>>(y0, envp, params, domain, out);
}

// round 13
// speedup vs baseline: 2.1927x; 1.0034x over previous
#include <cuda_runtime.h>
#include <math.h>

#define PI_D 3.14159265358979323846
#define CS 65              // padded stride for smem tables / fields
#define NTHR 256

typedef unsigned long long u64;

// packed f32x2 helpers (sm_100+ PTX)
#define FMA2(acc, a, b) asm("fma.rn.f32x2 %0, %1, %2, %0;" : "+l"(acc) : "l"(a), "l"(b))
#define PACK2(d, lo, hi) asm("mov.b64 %0, {%1, %2};" : "=l"(d) : "r"(__float_as_uint(lo)), "r"(__float_as_uint(hi)))
#define UNPACK2(lo, hi, s) do { unsigned _l, _h; \
    asm("mov.b64 {%0, %1}, %2;" : "=r"(_l), "=r"(_h) : "l"(s)); \
    lo = __uint_as_float(_l); hi = __uint_as_float(_h); } while (0)

__device__ float2 gCS[33*64];   // (cos, sin)(2*pi*k*n/65)
__device__ int    g_env_bad;    // 1 if env buffer is int32, 0 if int64

__global__ void init_tables_kernel() {
    int idx = blockIdx.x*blockDim.x + threadIdx.x;
    if (idx == 0) g_env_bad = 0;
    if (idx < 33*64) {
        int k = idx >> 6, n = idx & 63;
        double t = 2.0 * (double)(k*n) / 65.0;
        double s, c;
        sincospi(t, &s, &c);
        gCS[idx] = make_float2((float)c, (float)s);
    }
}

__global__ void detect_env_kernel(const long long* __restrict__ env) {
    int i = blockIdx.x*blockDim.x + threadIdx.x;
    if (i < 2048) {
        long long v = env[i];
        if (v < 0 || v >= 8) g_env_bad = 1;
    }
}

__global__ __launch_bounds__(NTHR, 3)
void turb_kernel(const float* __restrict__ y0, const void* __restrict__ envp,
                 const float* __restrict__ params, const float* __restrict__ domain,
                 float* __restrict__ out)
{
    extern __shared__ float smf[];
    float2* cs2  = (float2*)smf;            // [33][CS] packed (c,s): 4290 floats
    float*  xs   = smf + 4290;              // [64][CS] floats: 4160
    float*  bufA = smf + 8450;              // 4290 floats (T2 / V2)
    float*  bufB = smf + 12740;             // 4290 floats (u2 / psi)

    float2* T2 = (float2*)bufA;             // [64][33]
    float2* V2 = (float2*)bufA;             // [33][CS]
    float2* u2 = (float2*)bufB;             // [33][CS]
    float*  psi = bufB;                     // [64][CS]

    const int tid = threadIdx.x;
    const int b   = blockIdx.x;

    int e;
    if (g_env_bad) e = ((const int*)envp)[b];
    else           e = (int)(((const long long*)envp)[b]);
    const float fdx  = domain[e] * (float)(PI_D / 64.0);
    const float mu   = params[2*e];
    const float fdx2 = fdx * fdx;

    for (int i = tid; i < 33*64; i += NTHR) {
        int k = i >> 6, n = i & 63;
        cs2[k*CS + n] = gCS[i];
    }
    const float* xin = y0 + (size_t)b * 4096;
    for (int i = tid; i < 4096; i += NTHR)
        xs[(i>>6)*CS + (i & 63)] = xin[i];
    __syncthreads();

    // ---------- Stage 1: T[m][k] = sum_{n=0..64} xpad[m][n]*(c - i s), k=0..32 --
    // Conjugate-pair fold over (n, 65-n), n=1..32 (xpad[64]=x[0]); n=0 single.
    // contribution = c*A - i*s*B, A=x1+x2, B=x1-x2. P=(sum c*A, sum s*B).
    // Tile: thread = (mg 0..31, kg 0..7); m in {mg,mg+32}, k = kg+8*jj (k<=32).
    {
        const int mg = tid & 31;
        const int kg = tid >> 5;
        u64 P0[5], P1[5];
        #pragma unroll
        for (int j = 0; j < 5; j++) { P0[j] = 0ULL; P1[j] = 0ULL; }
        const float* xr0 = xs + mg*CS;
        const float* xr1 = xs + (mg+32)*CS;
        #pragma unroll 2
        for (int n = 1; n <= 32; n++) {
            int n2 = (65 - n) & 63;          // 64 -> 0 (pad wrap), else 65-n
            float x10 = xr0[n], x20 = xr0[n2];
            float x11 = xr1[n], x21 = xr1[n2];
            u64 AB0; PACK2(AB0, x10 + x20, x10 - x20);
            u64 AB1; PACK2(AB1, x11 + x21, x11 - x21);
            #pragma unroll
            for (int jj = 0; jj < 5; jj++) {
                if (jj < 4 || kg == 0) {
                    int k = kg + 8*jj;
                    u64 cs = *(const u64*)(cs2 + k*CS + n);
                    FMA2(P0[jj], AB0, cs);   // (sum c*A, sum s*B)
                    FMA2(P1[jj], AB1, cs);
                }
            }
        }
        float x00 = xr0[0], x01 = xr1[0];    // n=0 single: +(x0, 0)
        #pragma unroll
        for (int jj = 0; jj < 5; jj++) {
            if (jj < 4 || kg == 0) {
                int k = kg + 8*jj;
                float plo, phi; UNPACK2(plo, phi, P0[jj]);
                T2[mg*33 + k] = make_float2(plo + x00, -phi);
                UNPACK2(plo, phi, P1[jj]);
                T2[(mg+32)*33 + k] = make_float2(plo + x01, -phi);
            }
        }
    }
    __syncthreads();

    // ---------- Stage 2: wf[a][bc] = sum_{m=0..64} e^{-2pi i a m/65} Tpad[m][bc] -
    // Conjugate-pair fold over (m, 65-m), m=1..32 (Tpad[64]=T[0]); m=0 single.
    // Pair contribution (raw T words, sign sg applied in epilogue):
    //   re = c*(t1r+t2r) + sg*s*(t1i-t2i) ; im = sg*c*(t1i+t2i) - s*(t1r-t2r)
    //   P = (S.lo, D.hi) x (c,s) ; Q = (S.hi, D.lo) x (c,s)
    // Tile: thread = (apg 0..16, bcg 0..14); a in {2apg, 2apg+1}, bc = bcg + 15*jj.
    {
        const int bcg = tid % 15;
        const int apg = tid / 15;
        if (apg < 17) {
            const int a0 = 2*apg;
            const bool hasA1 = (a0 + 1 <= 32);
            const int a1 = hasA1 ? a0 + 1 : 32;
            int col[5]; float sg[5]; bool val[5];
            #pragma unroll
            for (int jj = 0; jj < 5; jj++) {
                int bc = bcg + 15*jj;
                val[jj] = (bc < 65);
                int bcc = val[jj] ? bc : 0;
                if (bcc <= 32) { col[jj] = bcc;      sg[jj] =  1.f; }
                else           { col[jj] = 65 - bcc; sg[jj] = -1.f; }
            }
            u64 P0[5], Q0[5], P1[5], Q1[5];
            #pragma unroll
            for (int jj = 0; jj < 5; jj++) { P0[jj]=0ULL; Q0[jj]=0ULL; P1[jj]=0ULL; Q1[jj]=0ULL; }
            #pragma unroll 2
            for (int m = 1; m <= 32; m++) {
                int m2 = (65 - m) & 63;       // 64 -> 0 (pad wrap), else 65-m
                u64 CS0 = *(const u64*)(cs2 + a0*CS + m);
                u64 CS1 = *(const u64*)(cs2 + a1*CS + m);
                const float2* Tr1 = T2 + m*33;
                const float2* Tr2 = T2 + m2*33;
                #pragma unroll
                for (int jj = 0; jj < 5; jj++) {
                    float2 t1 = Tr1[col[jj]];
                    float2 t2 = Tr2[col[jj]];
                    u64 Pop; PACK2(Pop, t1.x + t2.x, t1.y - t2.y);
                    u64 Qop; PACK2(Qop, t1.y + t2.y, t1.x - t2.x);
                    FMA2(P0[jj], Pop, CS0);   // (sum c*Sr, sum s*Di)
                    FMA2(Q0[jj], Qop, CS0);   // (sum c*Si, sum s*Dr)
                    FMA2(P1[jj], Pop, CS1);
                    FMA2(Q1[jj], Qop, CS1);
                }
            }
            const float K2f = (float)((2.0*PI_D/65.0) * (2.0*PI_D/65.0));
            #pragma unroll
            for (int jj = 0; jj < 5; jj++) {
                if (val[jj]) {
                    int bc = bcg + 15*jj;
                    float2 T0 = T2[col[jj]];            // m = 0 single term
                    float tr0 = T0.x, ti0 = sg[jj]*T0.y;
                    int jb = (bc <= 32) ? bc : bc - 65;
                    float jb2 = (float)(jb*jb);
                    {
                        float plo, phi; UNPACK2(plo, phi, P0[jj]);
                        float qlo, qhi; UNPACK2(qlo, qhi, Q0[jj]);
                        float wr = plo + sg[jj]*phi + tr0;
                        float wi = sg[jj]*qlo - qhi + ti0;
                        float c2 = K2f * ((float)(a0*a0) + jb2);
                        float sval = (a0 == 0 && bc == 0) ? 0.f
                                   : 1.0f / ((1e-12f + c2 / fdx2) * 4225.0f);
                        u2[a0*CS + bc] = make_float2(wr*sval, wi*sval);
                    }
                    if (hasA1) {
                        float plo, phi; UNPACK2(plo, phi, P1[jj]);
                        float qlo, qhi; UNPACK2(qlo, qhi, Q1[jj]);
                        float wr = plo + sg[jj]*phi + tr0;
                        float wi = sg[jj]*qlo - qhi + ti0;
                        float c2 = K2f * ((float)(a1*a1) + jb2);
                        float sval = 1.0f / ((1e-12f + c2 / fdx2) * 4225.0f);
                        u2[a1*CS + bc] = make_float2(wr*sval, wi*sval);
                    }
                }
            }
        }
    }
    __syncthreads();

    // ---------- Stage 3: V[a][n] = sum_{b=0..64} u[a][b] * e^{+2πibn/65} --------
    // Conjugate-pair fold over (b, 65-b), b=1..32; b=0 single.
    // contribution = c*A + i*s*B: re = c*Ar - s*Bi, im = c*Ai + s*Br.
    // P=(sum c*Ar, sum s*Bi) via FMA2(P,(Ar,Bi),cs); Q=(sum c*Ai, sum s*Br).
    // Tile: thread = (apg 0..16, ngrp 0..12); a in {2apg, 2apg+1}, n = ngrp*5+jj.
    {
        const int ngrp = tid % 13;
        const int apg  = tid / 13;
        if (apg < 17) {
            const int a0 = 2*apg;
            const bool hasA1 = (a0 + 1 <= 32);
            const int a1 = hasA1 ? a0 + 1 : 32;
            u64 P0[5], Q0[5], P1[5], Q1[5];
            #pragma unroll
            for (int jj = 0; jj < 5; jj++) { P0[jj]=0ULL; Q0[jj]=0ULL; P1[jj]=0ULL; Q1[jj]=0ULL; }
            const float2* ua0 = u2 + a0*CS;
            const float2* ua1 = u2 + a1*CS;
            #pragma unroll 2
            for (int bq = 1; bq <= 32; bq++) {
                float2 p0 = ua0[bq], q0 = ua0[65-bq];
                float2 p1 = ua1[bq], q1 = ua1[65-bq];
                u64 A0; PACK2(A0, p0.x + q0.x, p0.y - q0.y);   // (Ar, Bi)
                u64 B0; PACK2(B0, p0.y + q0.y, p0.x - q0.x);   // (Ai, Br)
                u64 A1; PACK2(A1, p1.x + q1.x, p1.y - q1.y);
                u64 B1; PACK2(B1, p1.y + q1.y, p1.x - q1.x);
                const float2* csrow = cs2 + bq*CS + ngrp*5;
                #pragma unroll
                for (int jj = 0; jj < 5; jj++) {
                    u64 cs = *(const u64*)(csrow + jj);
                    FMA2(P0[jj], A0, cs);
                    FMA2(Q0[jj], B0, cs);
                    FMA2(P1[jj], A1, cs);
                    FMA2(Q1[jj], B1, cs);
                }
            }
            float2 u00 = ua0[0], u01 = ua1[0];   // b=0 single
            #pragma unroll
            for (int jj = 0; jj < 5; jj++) {
                int n = ngrp*5 + jj;
                if (n < 64) {
                    float plo, phi; UNPACK2(plo, phi, P0[jj]);
                    float qlo, qhi; UNPACK2(qlo, qhi, Q0[jj]);
                    V2[a0*CS + n] = make_float2(plo - phi + u00.x, qlo + qhi + u00.y);
                    if (hasA1) {
                        UNPACK2(plo, phi, P1[jj]);
                        UNPACK2(qlo, qhi, Q1[jj]);
                        V2[a1*CS + n] = make_float2(plo - phi + u01.x, qlo + qhi + u01.y);
                    }
                }
            }
        }
    }
    __syncthreads();

    // ---------- Stage 4: psi[m][n] = Vr[0][n] + 2*sum_{a=1..32}(c*Vr - s*Vi) -----
    // Tile: thread = (mg 0..31, ngg 0..7); m in {mg, mg+32}, n = ngg + 8*j.
    {
        const int mg  = tid & 31;
        const int ngg = tid >> 5;   // 0..7
        u64 P0[8], P1[8];
        #pragma unroll
        for (int j = 0; j < 8; j++) { P0[j] = 0ULL; P1[j] = 0ULL; }
        #pragma unroll 2
        for (int a = 1; a < 33; a++) {
            u64 C0 = *(const u64*)(cs2 + a*CS + mg);
            u64 C1 = *(const u64*)(cs2 + a*CS + mg + 32);
            const float2* Vrow = V2 + a*CS + ngg;
            #pragma unroll
            for (int j = 0; j < 8; j++) {
                u64 V = *(const u64*)(Vrow + 8*j);
                FMA2(P0[j], C0, V);           // (c*Vr, s*Vi)
                FMA2(P1[j], C1, V);
            }
        }
        #pragma unroll
        for (int j = 0; j < 8; j++) {
            int n = ngg + 8*j;
            float v0r = V2[n].x;
            float plo, phi; UNPACK2(plo, phi, P0[j]);
            psi[mg*CS + n] = v0r + 2.0f*(plo - phi);
            UNPACK2(plo, phi, P1[j]);
            psi[(mg+32)*CS + n] = v0r + 2.0f*(plo - phi);
        }
    }
    __syncthreads();

    // ---------- Stencil: Arakawa Jacobian + laplacian, write dudt ---------------
    {
        float* o = out + (size_t)b * 4096;
        const float inv12 = 1.0f / (12.0f * fdx2);   // (1/(4 fdx2)) / 3
        const float mf    = mu / fdx2;
        #pragma unroll 2
        for (int idx = tid; idx < 4096; idx += NTHR) {
            int i  = idx >> 6, j = idx & 63;
            int ip = (i+1) & 63, im = (i-1) & 63;
            int jp = (j+1) & 63, jm = (j-1) & 63;
            float Pipj  = psi[ip*CS+j],  Pimj  = psi[im*CS+j];
            float Pijp  = psi[i*CS+jp],  Pijm  = psi[i*CS+jm];
            float Pipjp = psi[ip*CS+jp], Pipjm = psi[ip*CS+jm];
            float Pimjp = psi[im*CS+jp], Pimjm = psi[im*CS+jm];
            float Xc    = xs[i*CS+j];
            float Xipj  = xs[ip*CS+j],   Ximj  = xs[im*CS+j];
            float Xijp  = xs[i*CS+jp],   Xijm  = xs[i*CS+jm];
            float Xipjp = xs[ip*CS+jp],  Xipjm = xs[ip*CS+jm];
            float Ximjp = xs[im*CS+jp],  Ximjm = xs[im*CS+jm];
            float J1 = (Pipj - Pimj)*(Xijp - Xijm) - (Pijp - Pijm)*(Xipj - Ximj);
            float J2 = Xijp*(Pipjp - Pimjp) - Xijm*(Pipjm - Pimjm)
                     - Xipj*(Pipjp - Pipjm) + Ximj*(Pimjp - Pimjm);
            float J3 = Xipjp*(Pipj - Pijp) - Ximjm*(Pijm - Pimj)
                     - Xipjm*(Pipj - Pijm) + Ximjp*(Pijp - Pimj);
            float lap = Ximj + Xijm - 4.0f*Xc + Xijp + Xipjm + Xipj;
            o[idx] = -(J1 + J2 + J3)*inv12 + mf*lap;
        }
    }
}

extern "C" void kernel_launch(void* const* d_in, const int* in_sizes, int n_in,
                              void* d_out, int out_size) {
    // inputs (metadata order): t, y0, env, codes, params, domain
    const float* y0     = (const float*)d_in[1];
    const void*  envp   = d_in[2];
    const float* params = (const float*)d_in[4];
    const float* domain = (const float*)d_in[5];
    float* out = (float*)d_out;

    const int smemBytes = 17030 * (int)sizeof(float); // 68120 B
    cudaFuncSetAttribute(turb_kernel, cudaFuncAttributeMaxDynamicSharedMemorySize, smemBytes);

    init_tables_kernel<<<9, 256>>>();
    detect_env_kernel<<<8, 256>>>((const long long*)envp);
    turb_kernel<<<4096, NTHR, smemBytes>>>(y0, envp, params, domain, out);
}

// round 14
// speedup vs baseline: 2.3021x; 1.0499x over previous
#include <cuda_runtime.h>
#include <math.h>

#define PI_D 3.14159265358979323846
#define CS 65              // padded stride for smem tables / fields
#define NTHR 256

typedef unsigned long long u64;

// packed f32x2 helpers (sm_100+ PTX)
#define FMA2(acc, a, b) asm("fma.rn.f32x2 %0, %1, %2, %0;" : "+l"(acc) : "l"(a), "l"(b))
#define FMA2_3(d, a, b, c) asm("fma.rn.f32x2 %0, %1, %2, %3;" : "=l"(d) : "l"(a), "l"(b), "l"(c))
#define MUL2(d, a, b) asm("mul.rn.f32x2 %0, %1, %2;" : "=l"(d) : "l"(a), "l"(b))
#define ADD2(d, a, b) asm("add.rn.f32x2 %0, %1, %2;" : "=l"(d) : "l"(a), "l"(b))
#define PACK2(d, lo, hi) asm("mov.b64 %0, {%1, %2};" : "=l"(d) : "r"(__float_as_uint(lo)), "r"(__float_as_uint(hi)))
#define UNPACK2(lo, hi, s) do { unsigned _l, _h; \
    asm("mov.b64 {%0, %1}, %2;" : "=r"(_l), "=r"(_h) : "l"(s)); \
    lo = __uint_as_float(_l); hi = __uint_as_float(_h); } while (0)
// d = a - b  (packed), using NEG1 = (-1,-1)
#define SUB2(d, a, bb, NEG) asm("fma.rn.f32x2 %0, %1, %2, %3;" : "=l"(d) : "l"(bb), "l"(NEG), "l"(a))

__device__ float2 gCS[33*64];   // (cos, sin)(2*pi*k*n/65)
__device__ int    g_env_bad;    // 1 if env buffer is int32, 0 if int64

__global__ void init_tables_kernel() {
    int idx = blockIdx.x*blockDim.x + threadIdx.x;
    if (idx == 0) g_env_bad = 0;
    if (idx < 33*64) {
        int k = idx >> 6, n = idx & 63;
        double t = 2.0 * (double)(k*n) / 65.0;
        double s, c;
        sincospi(t, &s, &c);
        gCS[idx] = make_float2((float)c, (float)s);
    }
}

__global__ void detect_env_kernel(const long long* __restrict__ env) {
    int i = blockIdx.x*blockDim.x + threadIdx.x;
    if (i < 2048) {
        long long v = env[i];
        if (v < 0 || v >= 8) g_env_bad = 1;
    }
}

__global__ __launch_bounds__(NTHR, 3)
void turb_kernel(const float* __restrict__ y0, const void* __restrict__ envp,
                 const float* __restrict__ params, const float* __restrict__ domain,
                 float* __restrict__ out)
{
    extern __shared__ float smf[];
    float2* cs2  = (float2*)smf;            // [33][CS] packed (c,s): 4290 floats
    float*  xs   = smf + 4290;              // [64][CS] floats: 4160
    float*  bufA = smf + 8450;              // 4290 floats (T2 / V2)
    float*  bufB = smf + 12740;             // 4290 floats (u2 / psi)

    float2* T2 = (float2*)bufA;             // [64][33]
    float2* V2 = (float2*)bufA;             // [33][CS]
    float2* u2 = (float2*)bufB;             // [33][CS]
    float*  psi = bufB;                     // [64][CS]

    const int tid = threadIdx.x;
    const int b   = blockIdx.x;

    int e;
    if (g_env_bad) e = ((const int*)envp)[b];
    else           e = (int)(((const long long*)envp)[b]);
    const float fdx  = domain[e] * (float)(PI_D / 64.0);
    const float mu   = params[2*e];
    const float fdx2 = fdx * fdx;

    for (int i = tid; i < 33*64; i += NTHR) {
        int k = i >> 6, n = i & 63;
        cs2[k*CS + n] = gCS[i];
    }
    const float* xin = y0 + (size_t)b * 4096;
    for (int i = tid; i < 4096; i += NTHR)
        xs[(i>>6)*CS + (i & 63)] = xin[i];
    __syncthreads();

    // ---------- Stage 1: T[m][k] = sum_{n=0..64} xpad[m][n]*(c - i s), k=0..32 --
    // Conjugate-pair fold over (n, 65-n), n=1..32 (xpad[64]=x[0]); n=0 single.
    // contribution = c*A - i*s*B, A=x1+x2, B=x1-x2. P=(sum c*A, sum s*B).
    // Tile: thread = (mg 0..31, kg 0..7); m in {mg,mg+32}, k = kg+8*jj (k<=32).
    {
        const int mg = tid & 31;
        const int kg = tid >> 5;
        u64 P0[5], P1[5];
        #pragma unroll
        for (int j = 0; j < 5; j++) { P0[j] = 0ULL; P1[j] = 0ULL; }
        const float* xr0 = xs + mg*CS;
        const float* xr1 = xs + (mg+32)*CS;
        #pragma unroll 2
        for (int n = 1; n <= 32; n++) {
            int n2 = (65 - n) & 63;          // 64 -> 0 (pad wrap), else 65-n
            float x10 = xr0[n], x20 = xr0[n2];
            float x11 = xr1[n], x21 = xr1[n2];
            u64 AB0; PACK2(AB0, x10 + x20, x10 - x20);
            u64 AB1; PACK2(AB1, x11 + x21, x11 - x21);
            #pragma unroll
            for (int jj = 0; jj < 5; jj++) {
                if (jj < 4 || kg == 0) {
                    int k = kg + 8*jj;
                    u64 cs = *(const u64*)(cs2 + k*CS + n);
                    FMA2(P0[jj], AB0, cs);   // (sum c*A, sum s*B)
                    FMA2(P1[jj], AB1, cs);
                }
            }
        }
        float x00 = xr0[0], x01 = xr1[0];    // n=0 single: +(x0, 0)
        #pragma unroll
        for (int jj = 0; jj < 5; jj++) {
            if (jj < 4 || kg == 0) {
                int k = kg + 8*jj;
                float plo, phi; UNPACK2(plo, phi, P0[jj]);
                T2[mg*33 + k] = make_float2(plo + x00, -phi);
                UNPACK2(plo, phi, P1[jj]);
                T2[(mg+32)*33 + k] = make_float2(plo + x01, -phi);
            }
        }
    }
    __syncthreads();

    // ---------- Stage 2: wf[a][bc] = sum_{m=0..64} e^{-2pi i a m/65} Tpad[m][bc] -
    // Conjugate-pair fold over (m, 65-m), m=1..32 (Tpad[64]=T[0]); m=0 single.
    //   re = c*(t1r+t2r) + sg*s*(t1i-t2i) ; im = sg*c*(t1i+t2i) - s*(t1r-t2r)
    //   P = (S.lo, D.hi) x (c,s) ; Q = (S.hi, D.lo) x (c,s)
    // Tile 3a x 3bc: thread = (apg 0..10, bcg 0..21); a = 3*apg+aa, bc = bcg*3+jj.
    {
        const int bcg = tid % 22;
        const int apg = tid / 22;   // 0..11; active < 11
        if (apg < 11) {
            const int a0 = 3*apg;
            int col[3]; float sg[3]; bool val[3];
            #pragma unroll
            for (int jj = 0; jj < 3; jj++) {
                int bc = bcg*3 + jj;
                val[jj] = (bc < 65);
                int bcc = val[jj] ? bc : 0;
                if (bcc <= 32) { col[jj] = bcc;      sg[jj] =  1.f; }
                else           { col[jj] = 65 - bcc; sg[jj] = -1.f; }
            }
            u64 P[3][3], Q[3][3];
            #pragma unroll
            for (int aa = 0; aa < 3; aa++)
                #pragma unroll
                for (int jj = 0; jj < 3; jj++) { P[aa][jj] = 0ULL; Q[aa][jj] = 0ULL; }
            #pragma unroll 2
            for (int m = 1; m <= 32; m++) {
                int m2 = (65 - m) & 63;       // 64 -> 0 (pad wrap), else 65-m
                u64 CSa0 = *(const u64*)(cs2 + (a0+0)*CS + m);
                u64 CSa1 = *(const u64*)(cs2 + (a0+1)*CS + m);
                u64 CSa2 = *(const u64*)(cs2 + (a0+2)*CS + m);
                const float2* Tr1 = T2 + m*33;
                const float2* Tr2 = T2 + m2*33;
                #pragma unroll
                for (int jj = 0; jj < 3; jj++) {
                    float2 t1 = Tr1[col[jj]];
                    float2 t2 = Tr2[col[jj]];
                    u64 Pop; PACK2(Pop, t1.x + t2.x, t1.y - t2.y);
                    u64 Qop; PACK2(Qop, t1.y + t2.y, t1.x - t2.x);
                    FMA2(P[0][jj], Pop, CSa0);   // (sum c*Sr, sum s*Di)
                    FMA2(Q[0][jj], Qop, CSa0);   // (sum c*Si, sum s*Dr)
                    FMA2(P[1][jj], Pop, CSa1);
                    FMA2(Q[1][jj], Qop, CSa1);
                    FMA2(P[2][jj], Pop, CSa2);
                    FMA2(Q[2][jj], Qop, CSa2);
                }
            }
            const float K2f = (float)((2.0*PI_D/65.0) * (2.0*PI_D/65.0));
            #pragma unroll
            for (int jj = 0; jj < 3; jj++) {
                if (val[jj]) {
                    int bc = bcg*3 + jj;
                    float2 T0 = T2[col[jj]];            // m = 0 single term
                    float tr0 = T0.x, ti0 = sg[jj]*T0.y;
                    int jb = (bc <= 32) ? bc : bc - 65;
                    float jb2 = (float)(jb*jb);
                    #pragma unroll
                    for (int aa = 0; aa < 3; aa++) {
                        int a = a0 + aa;
                        float plo, phi; UNPACK2(plo, phi, P[aa][jj]);
                        float qlo, qhi; UNPACK2(qlo, qhi, Q[aa][jj]);
                        float wr = plo + sg[jj]*phi + tr0;
                        float wi = sg[jj]*qlo - qhi + ti0;
                        float c2 = K2f * ((float)(a*a) + jb2);
                        float sval = (a == 0 && bc == 0) ? 0.f
                                   : 1.0f / ((1e-12f + c2 / fdx2) * 4225.0f);
                        u2[a*CS + bc] = make_float2(wr*sval, wi*sval);
                    }
                }
            }
        }
    }
    __syncthreads();

    // ---------- Stage 3: V[a][n] = sum_{b=0..64} u[a][b] * e^{+2πibn/65} --------
    // Conjugate-pair fold over (b, 65-b), b=1..32; b=0 single.
    // contribution = c*A + i*s*B: re = c*Ar - s*Bi, im = c*Ai + s*Br.
    // Tile: thread = (apg 0..16, ngrp 0..12); a in {2apg, 2apg+1}, n = ngrp*5+jj.
    {
        const int ngrp = tid % 13;
        const int apg  = tid / 13;
        if (apg < 17) {
            const int a0 = 2*apg;
            const bool hasA1 = (a0 + 1 <= 32);
            const int a1 = hasA1 ? a0 + 1 : 32;
            u64 P0[5], Q0[5], P1[5], Q1[5];
            #pragma unroll
            for (int jj = 0; jj < 5; jj++) { P0[jj]=0ULL; Q0[jj]=0ULL; P1[jj]=0ULL; Q1[jj]=0ULL; }
            const float2* ua0 = u2 + a0*CS;
            const float2* ua1 = u2 + a1*CS;
            #pragma unroll 2
            for (int bq = 1; bq <= 32; bq++) {
                float2 p0 = ua0[bq], q0 = ua0[65-bq];
                float2 p1 = ua1[bq], q1 = ua1[65-bq];
                u64 A0; PACK2(A0, p0.x + q0.x, p0.y - q0.y);   // (Ar, Bi)
                u64 B0; PACK2(B0, p0.y + q0.y, p0.x - q0.x);   // (Ai, Br)
                u64 A1; PACK2(A1, p1.x + q1.x, p1.y - q1.y);
                u64 B1; PACK2(B1, p1.y + q1.y, p1.x - q1.x);
                const float2* csrow = cs2 + bq*CS + ngrp*5;
                #pragma unroll
                for (int jj = 0; jj < 5; jj++) {
                    u64 cs = *(const u64*)(csrow + jj);
                    FMA2(P0[jj], A0, cs);
                    FMA2(Q0[jj], B0, cs);
                    FMA2(P1[jj], A1, cs);
                    FMA2(Q1[jj], B1, cs);
                }
            }
            float2 u00 = ua0[0], u01 = ua1[0];   // b=0 single
            #pragma unroll
            for (int jj = 0; jj < 5; jj++) {
                int n = ngrp*5 + jj;
                if (n < 64) {
                    float plo, phi; UNPACK2(plo, phi, P0[jj]);
                    float qlo, qhi; UNPACK2(qlo, qhi, Q0[jj]);
                    V2[a0*CS + n] = make_float2(plo - phi + u00.x, qlo + qhi + u00.y);
                    if (hasA1) {
                        UNPACK2(plo, phi, P1[jj]);
                        UNPACK2(qlo, qhi, Q1[jj]);
                        V2[a1*CS + n] = make_float2(plo - phi + u01.x, qlo + qhi + u01.y);
                    }
                }
            }
        }
    }
    __syncthreads();

    // ---------- Stage 4: psi[m][n] = Vr[0][n] + 2*sum_{a=1..32}(c*Vr - s*Vi) -----
    // Tile: thread = (mg 0..31, ngg 0..7); m in {mg, mg+32}, n = ngg + 8*j.
    {
        const int mg  = tid & 31;
        const int ngg = tid >> 5;   // 0..7
        u64 P0[8], P1[8];
        #pragma unroll
        for (int j = 0; j < 8; j++) { P0[j] = 0ULL; P1[j] = 0ULL; }
        #pragma unroll 2
        for (int a = 1; a < 33; a++) {
            u64 C0 = *(const u64*)(cs2 + a*CS + mg);
            u64 C1 = *(const u64*)(cs2 + a*CS + mg + 32);
            const float2* Vrow = V2 + a*CS + ngg;
            #pragma unroll
            for (int j = 0; j < 8; j++) {
                u64 V = *(const u64*)(Vrow + 8*j);
                FMA2(P0[j], C0, V);           // (c*Vr, s*Vi)
                FMA2(P1[j], C1, V);
            }
        }
        #pragma unroll
        for (int j = 0; j < 8; j++) {
            int n = ngg + 8*j;
            float v0r = V2[n].x;
            float plo, phi; UNPACK2(plo, phi, P0[j]);
            psi[mg*CS + n] = v0r + 2.0f*(plo - phi);
            UNPACK2(plo, phi, P1[j]);
            psi[(mg+32)*CS + n] = v0r + 2.0f*(plo - phi);
        }
    }
    __syncthreads();

    // ---------- Stencil: Arakawa Jacobian + laplacian, packed column pairs ------
    // Thread handles outputs (i, j) and (i, j+1), j even. All math in f32x2.
    {
        float* o = out + (size_t)b * 4096;
        const float inv12 = 1.0f / (12.0f * fdx2);   // (1/(4 fdx2)) / 3
        const float mf    = mu / fdx2;
        u64 NEG1;  PACK2(NEG1,  -1.0f, -1.0f);
        u64 NFOUR; PACK2(NFOUR, -4.0f, -4.0f);
        u64 NINV12; PACK2(NINV12, -inv12, -inv12);
        u64 MF2;   PACK2(MF2, mf, mf);
        #pragma unroll 2
        for (int t = 0; t < 8; t++) {
            int pidx = tid + t*NTHR;          // 0..2047
            int i = pidx >> 5;                // row 0..63
            int j = (pidx & 31) << 1;         // even col 0..62
            int ip = (i+1) & 63, im = (i-1) & 63;
            int jm = (j-1) & 63, jp2 = (j+2) & 63;   // j+1 <= 63 always
            const float* Pi = psi + i*CS;  const float* Pp = psi + ip*CS;  const float* Pm = psi + im*CS;
            const float* Xi = xs  + i*CS;  const float* Xp = xs  + ip*CS;  const float* Xm = xs  + im*CS;
            float pi_m = Pi[jm], pi_0 = Pi[j], pi_1 = Pi[j+1], pi_2 = Pi[jp2];
            float pp_m = Pp[jm], pp_0 = Pp[j], pp_1 = Pp[j+1], pp_2 = Pp[jp2];
            float pm_m = Pm[jm], pm_0 = Pm[j], pm_1 = Pm[j+1], pm_2 = Pm[jp2];
            float xi_m = Xi[jm], xi_0 = Xi[j], xi_1 = Xi[j+1], xi_2 = Xi[jp2];
            float xp_m = Xp[jm], xp_0 = Xp[j], xp_1 = Xp[j+1], xp_2 = Xp[jp2];
            float xm_m = Xm[jm], xm_0 = Xm[j], xm_1 = Xm[j+1], xm_2 = Xm[jp2];
            u64 Pipj;  PACK2(Pipj,  pp_0, pp_1);
            u64 Pimj;  PACK2(Pimj,  pm_0, pm_1);
            u64 Pijp;  PACK2(Pijp,  pi_1, pi_2);
            u64 Pijm;  PACK2(Pijm,  pi_m, pi_0);
            u64 Pipjp; PACK2(Pipjp, pp_1, pp_2);
            u64 Pipjm; PACK2(Pipjm, pp_m, pp_0);
            u64 Pimjp; PACK2(Pimjp, pm_1, pm_2);
            u64 Pimjm; PACK2(Pimjm, pm_m, pm_0);
            u64 Xc2;   PACK2(Xc2,   xi_0, xi_1);
            u64 Xipj;  PACK2(Xipj,  xp_0, xp_1);
            u64 Ximj;  PACK2(Ximj,  xm_0, xm_1);
            u64 Xijp;  PACK2(Xijp,  xi_1, xi_2);
            u64 Xijm;  PACK2(Xijm,  xi_m, xi_0);
            u64 Xipjp; PACK2(Xipjp, xp_1, xp_2);
            u64 Xipjm; PACK2(Xipjm, xp_m, xp_0);
            u64 Ximjp; PACK2(Ximjp, xm_1, xm_2);
            u64 Ximjm; PACK2(Ximjm, xm_m, xm_0);
            // J1
            u64 dPj; SUB2(dPj, Pipj, Pimj, NEG1);
            u64 dXj; SUB2(dXj, Xijp, Xijm, NEG1);
            u64 dPi; SUB2(dPi, Pijp, Pijm, NEG1);
            u64 dXi; SUB2(dXi, Xipj, Ximj, NEG1);
            u64 acc; MUL2(acc, dPj, dXj);
            u64 tm;  MUL2(tm, dPi, dXi);
            SUB2(acc, acc, tm, NEG1);
            // J2
            u64 d1; SUB2(d1, Pipjp, Pimjp, NEG1);
            u64 d2; SUB2(d2, Pipjm, Pimjm, NEG1);
            u64 d3; SUB2(d3, Pipjp, Pipjm, NEG1);
            u64 d4; SUB2(d4, Pimjp, Pimjm, NEG1);
            FMA2_3(acc, Xijp, d1, acc);
            MUL2(tm, Xijm, d2); SUB2(acc, acc, tm, NEG1);
            MUL2(tm, Xipj, d3); SUB2(acc, acc, tm, NEG1);
            FMA2_3(acc, Ximj, d4, acc);
            // J3
            u64 e1; SUB2(e1, Pipj, Pijp, NEG1);
            u64 e2; SUB2(e2, Pijm, Pimj, NEG1);
            u64 e3; SUB2(e3, Pipj, Pijm, NEG1);
            u64 e4; SUB2(e4, Pijp, Pimj, NEG1);
            FMA2_3(acc, Xipjp, e1, acc);
            MUL2(tm, Ximjm, e2); SUB2(acc, acc, tm, NEG1);
            MUL2(tm, Xipjm, e3); SUB2(acc, acc, tm, NEG1);
            FMA2_3(acc, Ximjp, e4, acc);
            // laplacian = Ximj + Xijm - 4*Xc + Xijp + Xipjm + Xipj
            u64 lap; ADD2(lap, Ximj, Xijm);
            ADD2(lap, lap, Xijp);
            ADD2(lap, lap, Xipjm);
            ADD2(lap, lap, Xipj);
            FMA2_3(lap, Xc2, NFOUR, lap);
            // out = -(J1+J2+J3)*inv12 + mf*lap
            u64 res; MUL2(res, lap, MF2);
            FMA2_3(res, acc, NINV12, res);
            float rlo, rhi; UNPACK2(rlo, rhi, res);
            *(float2*)(o + i*64 + j) = make_float2(rlo, rhi);
        }
    }
}

extern "C" void kernel_launch(void* const* d_in, const int* in_sizes, int n_in,
                              void* d_out, int out_size) {
    // inputs (metadata order): t, y0, env, codes, params, domain
    const float* y0     = (const float*)d_in[1];
    const void*  envp   = d_in[2];
    const float* params = (const float*)d_in[4];
    const float* domain = (const float*)d_in[5];
    float* out = (float*)d_out;

    const int smemBytes = 17030 * (int)sizeof(float); // 68120 B
    cudaFuncSetAttribute(turb_kernel, cudaFuncAttributeMaxDynamicSharedMemorySize, smemBytes);

    init_tables_kernel<<<9, 256>>>();
    detect_env_kernel<<<8, 256>>>((const long long*)envp);
    turb_kernel<<<4096, NTHR, smemBytes>>>(y0, envp, params, domain, out);
}

// round 15
// speedup vs baseline: 2.9867x; 1.2974x over previous
#include <cuda_runtime.h>
#include <math.h>

#define PI_D 3.14159265358979323846
#define CS 65              // padded stride for smem tables / fields
#define NTHR 256

typedef unsigned long long u64;

// packed f32x2 helpers (sm_100+ PTX)
#define FMA2(acc, a, b) asm("fma.rn.f32x2 %0, %1, %2, %0;" : "+l"(acc) : "l"(a), "l"(b))
#define FMA2_3(d, a, b, c) asm("fma.rn.f32x2 %0, %1, %2, %3;" : "=l"(d) : "l"(a), "l"(b), "l"(c))
#define MUL2(d, a, b) asm("mul.rn.f32x2 %0, %1, %2;" : "=l"(d) : "l"(a), "l"(b))
#define ADD2(d, a, b) asm("add.rn.f32x2 %0, %1, %2;" : "=l"(d) : "l"(a), "l"(b))
#define PACK2(d, lo, hi) asm("mov.b64 %0, {%1, %2};" : "=l"(d) : "r"(__float_as_uint(lo)), "r"(__float_as_uint(hi)))
#define UNPACK2(lo, hi, s) do { unsigned _l, _h; \
    asm("mov.b64 {%0, %1}, %2;" : "=r"(_l), "=r"(_h) : "l"(s)); \
    lo = __uint_as_float(_l); hi = __uint_as_float(_h); } while (0)
// d = a - b  (packed), using NEG1 = (-1,-1)
#define SUB2(d, a, bb, NEG) asm("fma.rn.f32x2 %0, %1, %2, %3;" : "=l"(d) : "l"(bb), "l"(NEG), "l"(a))

__device__ float2 gCS[33*64];   // (cos, sin)(2*pi*k*n/65)
__device__ int    g_env_bad;    // 1 if env buffer is int32, 0 if int64

__global__ void init_tables_kernel() {
    int idx = blockIdx.x*blockDim.x + threadIdx.x;
    if (idx == 0) g_env_bad = 0;
    if (idx < 33*64) {
        int k = idx >> 6, n = idx & 63;
        double t = 2.0 * (double)(k*n) / 65.0;
        double s, c;
        sincospi(t, &s, &c);
        gCS[idx] = make_float2((float)c, (float)s);
    }
}

__global__ void detect_env_kernel(const long long* __restrict__ env) {
    int i = blockIdx.x*blockDim.x + threadIdx.x;
    if (i < 2048) {
        long long v = env[i];
        if (v < 0 || v >= 8) g_env_bad = 1;
    }
}

__global__ __launch_bounds__(NTHR, 3)
void turb_kernel(const float* __restrict__ y0, const void* __restrict__ envp,
                 const float* __restrict__ params, const float* __restrict__ domain,
                 float* __restrict__ out)
{
    extern __shared__ float smf[];
    float2* cs2  = (float2*)smf;            // [33][CS] packed (c,s): 4290 floats
    float*  xs   = smf + 4290;              // [64][CS] floats: 4160
    float*  bufA = smf + 8450;              // 4290 floats (T2 / V2)
    float*  bufB = smf + 12740;             // 4290 floats (u2 / psi)

    float2* T2 = (float2*)bufA;             // [64][33]
    float2* V2 = (float2*)bufA;             // [33][CS]
    float2* u2 = (float2*)bufB;             // [33][CS]
    float*  psi = bufB;                     // [64][CS]

    const int tid = threadIdx.x;
    const int b   = blockIdx.x;

    int e;
    if (g_env_bad) e = ((const int*)envp)[b];
    else           e = (int)(((const long long*)envp)[b]);
    const float fdx  = domain[e] * (float)(PI_D / 64.0);
    const float mu   = params[2*e];
    const float fdx2 = fdx * fdx;

    // only columns 0..32 of the table are ever read
    for (int i = tid; i < 33*33; i += NTHR) {
        int k = i / 33, n = i % 33;
        cs2[k*CS + n] = gCS[(k<<6) + n];
    }
    const float* xin = y0 + (size_t)b * 4096;
    for (int i = tid; i < 4096; i += NTHR)
        xs[(i>>6)*CS + (i & 63)] = xin[i];
    __syncthreads();

    // ---------- Stage 1: T[m][k] = sum_{n=0..64} xpad[m][n]*(c - i s), k=0..32 --
    // Conjugate-pair fold over (n, 65-n), n=1..32 (xpad[64]=x[0]); n=0 single.
    // contribution = c*A - i*s*B, A=x1+x2, B=x1-x2. P=(sum c*A, sum s*B).
    // Tile: thread = (mg 0..31, kg 0..7); m in {mg,mg+32}, k = kg+8*jj (k<=32).
    {
        const int mg = tid & 31;
        const int kg = tid >> 5;
        u64 P0[5], P1[5];
        #pragma unroll
        for (int j = 0; j < 5; j++) { P0[j] = 0ULL; P1[j] = 0ULL; }
        const float* xr0 = xs + mg*CS;
        const float* xr1 = xs + (mg+32)*CS;
        #pragma unroll 2
        for (int n = 1; n <= 32; n++) {
            int n2 = (65 - n) & 63;          // 64 -> 0 (pad wrap), else 65-n
            float x10 = xr0[n], x20 = xr0[n2];
            float x11 = xr1[n], x21 = xr1[n2];
            u64 AB0; PACK2(AB0, x10 + x20, x10 - x20);
            u64 AB1; PACK2(AB1, x11 + x21, x11 - x21);
            #pragma unroll
            for (int jj = 0; jj < 5; jj++) {
                if (jj < 4 || kg == 0) {
                    int k = kg + 8*jj;
                    u64 cs = *(const u64*)(cs2 + k*CS + n);
                    FMA2(P0[jj], AB0, cs);   // (sum c*A, sum s*B)
                    FMA2(P1[jj], AB1, cs);
                }
            }
        }
        float x00 = xr0[0], x01 = xr1[0];    // n=0 single: +(x0, 0)
        #pragma unroll
        for (int jj = 0; jj < 5; jj++) {
            if (jj < 4 || kg == 0) {
                int k = kg + 8*jj;
                float plo, phi; UNPACK2(plo, phi, P0[jj]);
                T2[mg*33 + k] = make_float2(plo + x00, -phi);
                UNPACK2(plo, phi, P1[jj]);
                T2[(mg+32)*33 + k] = make_float2(plo + x01, -phi);
            }
        }
    }
    __syncthreads();

    // ---------- Stage 2: wf[a][bc] = sum_{m=0..64} e^{-2pi i a m/65} Tpad[m][bc] -
    // m-fold over (m, 65-m), m=1..32 (Tpad[64]=T[0]); m=0 single.
    // OUTPUT fold: bc=col and bc=65-col share P,Q:
    //   P = (Sr, Di) x (c,s) ; Q = (Si, Dr) x (c,s)
    //   wr(+)=plo+phi+T0.x  wi(+)= qlo-qhi+T0.y   (bc=col)
    //   wr(-)=plo-phi+T0.x  wi(-)=-qlo-qhi-T0.y   (bc=65-col)
    // Tile 3a x 3col: 121 threads (apg 0..10, colg 0..10).
    {
        const int colg = tid % 11;
        const int apg  = tid / 11;   // active < 11
        if (apg < 11) {
            const int a0 = 3*apg;
            const int c0 = 3*colg;
            u64 P[3][3], Q[3][3];
            #pragma unroll
            for (int aa = 0; aa < 3; aa++)
                #pragma unroll
                for (int cc = 0; cc < 3; cc++) { P[aa][cc] = 0ULL; Q[aa][cc] = 0ULL; }
            #pragma unroll 2
            for (int m = 1; m <= 32; m++) {
                int m2 = (65 - m) & 63;       // 64 -> 0 (pad wrap), else 65-m
                u64 CSa0 = *(const u64*)(cs2 + (a0+0)*CS + m);
                u64 CSa1 = *(const u64*)(cs2 + (a0+1)*CS + m);
                u64 CSa2 = *(const u64*)(cs2 + (a0+2)*CS + m);
                const float2* Tr1 = T2 + m*33;
                const float2* Tr2 = T2 + m2*33;
                #pragma unroll
                for (int cc = 0; cc < 3; cc++) {
                    float2 t1 = Tr1[c0+cc];
                    float2 t2 = Tr2[c0+cc];
                    u64 Pop; PACK2(Pop, t1.x + t2.x, t1.y - t2.y);
                    u64 Qop; PACK2(Qop, t1.y + t2.y, t1.x - t2.x);
                    FMA2(P[0][cc], Pop, CSa0);   // (sum c*Sr, sum s*Di)
                    FMA2(Q[0][cc], Qop, CSa0);   // (sum c*Si, sum s*Dr)
                    FMA2(P[1][cc], Pop, CSa1);
                    FMA2(Q[1][cc], Qop, CSa1);
                    FMA2(P[2][cc], Pop, CSa2);
                    FMA2(Q[2][cc], Qop, CSa2);
                }
            }
            const float K2f = (float)((2.0*PI_D/65.0) * (2.0*PI_D/65.0));
            #pragma unroll
            for (int cc = 0; cc < 3; cc++) {
                int col = c0 + cc;
                float2 T0 = T2[col];            // m = 0 single term
                float col2 = (float)(col*col);
                #pragma unroll
                for (int aa = 0; aa < 3; aa++) {
                    int a = a0 + aa;
                    float plo, phi; UNPACK2(plo, phi, P[aa][cc]);
                    float qlo, qhi; UNPACK2(qlo, qhi, Q[aa][cc]);
                    float c2 = K2f * ((float)(a*a) + col2);
                    float sval = (a == 0 && col == 0) ? 0.f
                               : 1.0f / ((1e-12f + c2 / fdx2) * 4225.0f);
                    float wr1 = plo + phi + T0.x;
                    float wi1 = qlo - qhi + T0.y;
                    u2[a*CS + col] = make_float2(wr1*sval, wi1*sval);
                    if (col > 0) {
                        float wr2 = plo - phi + T0.x;
                        float wi2 = -qlo - qhi - T0.y;
                        u2[a*CS + 65 - col] = make_float2(wr2*sval, wi2*sval);
                    }
                }
            }
        }
    }
    __syncthreads();

    // ---------- Stage 3: V[a][n] = sum_{b=0..64} u[a][b] * e^{+2πibn/65} --------
    // b-fold over (b, 65-b), b=1..32; b=0 single.
    // OUTPUT fold: n and 65-n share P,Q (cos even, sin odd in n):
    //   V[a][n]    = (plo-phi+u0.x, qlo+qhi+u0.y)
    //   V[a][65-n] = (plo+phi+u0.x, qlo-qhi+u0.y)   (n >= 2; 65-n in 33..63)
    // Tile 3a x 3ncol: 121 threads (apg 0..10, colg 0..10).
    {
        const int colg = tid % 11;
        const int apg  = tid / 11;   // active < 11
        if (apg < 11) {
            const int a0 = 3*apg;
            const int n0 = 3*colg;
            u64 P[3][3], Q[3][3];
            #pragma unroll
            for (int aa = 0; aa < 3; aa++)
                #pragma unroll
                for (int cc = 0; cc < 3; cc++) { P[aa][cc] = 0ULL; Q[aa][cc] = 0ULL; }
            const float2* ua0 = u2 + (a0+0)*CS;
            const float2* ua1 = u2 + (a0+1)*CS;
            const float2* ua2 = u2 + (a0+2)*CS;
            #pragma unroll 2
            for (int bq = 1; bq <= 32; bq++) {
                float2 p0 = ua0[bq], q0 = ua0[65-bq];
                float2 p1 = ua1[bq], q1 = ua1[65-bq];
                float2 p2 = ua2[bq], q2 = ua2[65-bq];
                u64 A0; PACK2(A0, p0.x + q0.x, p0.y - q0.y);   // (Ar, Bi)
                u64 B0; PACK2(B0, p0.y + q0.y, p0.x - q0.x);   // (Ai, Br)
                u64 A1; PACK2(A1, p1.x + q1.x, p1.y - q1.y);
                u64 B1; PACK2(B1, p1.y + q1.y, p1.x - q1.x);
                u64 A2; PACK2(A2, p2.x + q2.x, p2.y - q2.y);
                u64 B2; PACK2(B2, p2.y + q2.y, p2.x - q2.x);
                const float2* csrow = cs2 + bq*CS + n0;
                #pragma unroll
                for (int cc = 0; cc < 3; cc++) {
                    u64 cs = *(const u64*)(csrow + cc);
                    FMA2(P[0][cc], A0, cs);   // (sum c*Ar, sum s*Bi)
                    FMA2(Q[0][cc], B0, cs);   // (sum c*Ai, sum s*Br)
                    FMA2(P[1][cc], A1, cs);
                    FMA2(Q[1][cc], B1, cs);
                    FMA2(P[2][cc], A2, cs);
                    FMA2(Q[2][cc], B2, cs);
                }
            }
            float2 u00 = ua0[0], u01 = ua1[0], u02 = ua2[0];   // b=0 single
            #pragma unroll
            for (int aa = 0; aa < 3; aa++) {
                int a = a0 + aa;
                float2 u0 = (aa == 0) ? u00 : ((aa == 1) ? u01 : u02);
                #pragma unroll
                for (int cc = 0; cc < 3; cc++) {
                    int n = n0 + cc;
                    float plo, phi; UNPACK2(plo, phi, P[aa][cc]);
                    float qlo, qhi; UNPACK2(qlo, qhi, Q[aa][cc]);
                    V2[a*CS + n] = make_float2(plo - phi + u0.x, qlo + qhi + u0.y);
                    if (n >= 2)
                        V2[a*CS + 65 - n] = make_float2(plo + phi + u0.x, qlo - qhi + u0.y);
                }
            }
        }
    }
    __syncthreads();

    // ---------- Stage 4: psi rows, m-OUTPUT fold ---------------------------------
    // psi[m][n] = Vr[0][n] + 2*(E - O), psi[65-m][n] = Vr[0][n] + 2*(E + O)
    // with P=(E,O)=(sum c*Vr, sum s*Vi) over a=1..32; mcol=0 single, mcol=1 no pair.
    // Tile 3mcol x 4n: mcg = tid&15 (<11), ngq = tid>>4 (0..15). 176 active, spread.
    {
        const int mcg = tid & 15;
        const int ngq = tid >> 4;    // 0..15
        if (mcg < 11) {
            const int m0 = 3*mcg;
            u64 P[3][4];
            #pragma unroll
            for (int mm = 0; mm < 3; mm++)
                #pragma unroll
                for (int jj = 0; jj < 4; jj++) P[mm][jj] = 0ULL;
            #pragma unroll 2
            for (int a = 1; a < 33; a++) {
                u64 C0 = *(const u64*)(cs2 + a*CS + m0 + 0);
                u64 C1 = *(const u64*)(cs2 + a*CS + m0 + 1);
                u64 C2 = *(const u64*)(cs2 + a*CS + m0 + 2);
                const float2* Vrow = V2 + a*CS + ngq*4;
                #pragma unroll
                for (int jj = 0; jj < 4; jj++) {
                    u64 V = *(const u64*)(Vrow + jj);
                    FMA2(P[0][jj], C0, V);       // (c*Vr, s*Vi)
                    FMA2(P[1][jj], C1, V);
                    FMA2(P[2][jj], C2, V);
                }
            }
            #pragma unroll
            for (int jj = 0; jj < 4; jj++) {
                int n = ngq*4 + jj;
                float v0r = V2[n].x;
                #pragma unroll
                for (int mm = 0; mm < 3; mm++) {
                    int mcol = m0 + mm;
                    float plo, phi; UNPACK2(plo, phi, P[mm][jj]);
                    psi[mcol*CS + n] = v0r + 2.0f*(plo - phi);
                    if (mcol >= 2)
                        psi[(65 - mcol)*CS + n] = v0r + 2.0f*(plo + phi);
                }
            }
        }
    }
    __syncthreads();

    // ---------- Stencil: Arakawa Jacobian + laplacian, packed column pairs ------
    // Thread handles outputs (i, j) and (i, j+1), j even. All math in f32x2.
    {
        float* o = out + (size_t)b * 4096;
        const float inv12 = 1.0f / (12.0f * fdx2);   // (1/(4 fdx2)) / 3
        const float mf    = mu / fdx2;
        u64 NEG1;  PACK2(NEG1,  -1.0f, -1.0f);
        u64 NFOUR; PACK2(NFOUR, -4.0f, -4.0f);
        u64 NINV12; PACK2(NINV12, -inv12, -inv12);
        u64 MF2;   PACK2(MF2, mf, mf);
        #pragma unroll 2
        for (int t = 0; t < 8; t++) {
            int pidx = tid + t*NTHR;          // 0..2047
            int i = pidx >> 5;                // row 0..63
            int j = (pidx & 31) << 1;         // even col 0..62
            int ip = (i+1) & 63, im = (i-1) & 63;
            int jm = (j-1) & 63, jp2 = (j+2) & 63;   // j+1 <= 63 always
            const float* Pi = psi + i*CS;  const float* Pp = psi + ip*CS;  const float* Pm = psi + im*CS;
            const float* Xi = xs  + i*CS;  const float* Xp = xs  + ip*CS;  const float* Xm = xs  + im*CS;
            float pi_m = Pi[jm], pi_0 = Pi[j], pi_1 = Pi[j+1], pi_2 = Pi[jp2];
            float pp_m = Pp[jm], pp_0 = Pp[j], pp_1 = Pp[j+1], pp_2 = Pp[jp2];
            float pm_m = Pm[jm], pm_0 = Pm[j], pm_1 = Pm[j+1], pm_2 = Pm[jp2];
            float xi_m = Xi[jm], xi_0 = Xi[j], xi_1 = Xi[j+1], xi_2 = Xi[jp2];
            float xp_m = Xp[jm], xp_0 = Xp[j], xp_1 = Xp[j+1], xp_2 = Xp[jp2];
            float xm_m = Xm[jm], xm_0 = Xm[j], xm_1 = Xm[j+1], xm_2 = Xm[jp2];
            u64 Pipj;  PACK2(Pipj,  pp_0, pp_1);
            u64 Pimj;  PACK2(Pimj,  pm_0, pm_1);
            u64 Pijp;  PACK2(Pijp,  pi_1, pi_2);
            u64 Pijm;  PACK2(Pijm,  pi_m, pi_0);
            u64 Pipjp; PACK2(Pipjp, pp_1, pp_2);
            u64 Pipjm; PACK2(Pipjm, pp_m, pp_0);
            u64 Pimjp; PACK2(Pimjp, pm_1, pm_2);
            u64 Pimjm; PACK2(Pimjm, pm_m, pm_0);
            u64 Xc2;   PACK2(Xc2,   xi_0, xi_1);
            u64 Xipj;  PACK2(Xipj,  xp_0, xp_1);
            u64 Ximj;  PACK2(Ximj,  xm_0, xm_1);
            u64 Xijp;  PACK2(Xijp,  xi_1, xi_2);
            u64 Xijm;  PACK2(Xijm,  xi_m, xi_0);
            u64 Xipjp; PACK2(Xipjp, xp_1, xp_2);
            u64 Xipjm; PACK2(Xipjm, xp_m, xp_0);
            u64 Ximjp; PACK2(Ximjp, xm_1, xm_2);
            u64 Ximjm; PACK2(Ximjm, xm_m, xm_0);
            // J1
            u64 dPj; SUB2(dPj, Pipj, Pimj, NEG1);
            u64 dXj; SUB2(dXj, Xijp, Xijm, NEG1);
            u64 dPi; SUB2(dPi, Pijp, Pijm, NEG1);
            u64 dXi; SUB2(dXi, Xipj, Ximj, NEG1);
            u64 acc; MUL2(acc, dPj, dXj);
            u64 tm;  MUL2(tm, dPi, dXi);
            SUB2(acc, acc, tm, NEG1);
            // J2
            u64 d1; SUB2(d1, Pipjp, Pimjp, NEG1);
            u64 d2; SUB2(d2, Pipjm, Pimjm, NEG1);
            u64 d3; SUB2(d3, Pipjp, Pipjm, NEG1);
            u64 d4; SUB2(d4, Pimjp, Pimjm, NEG1);
            FMA2_3(acc, Xijp, d1, acc);
            MUL2(tm, Xijm, d2); SUB2(acc, acc, tm, NEG1);
            MUL2(tm, Xipj, d3); SUB2(acc, acc, tm, NEG1);
            FMA2_3(acc, Ximj, d4, acc);
            // J3
            u64 e1; SUB2(e1, Pipj, Pijp, NEG1);
            u64 e2; SUB2(e2, Pijm, Pimj, NEG1);
            u64 e3; SUB2(e3, Pipj, Pijm, NEG1);
            u64 e4; SUB2(e4, Pijp, Pimj, NEG1);
            FMA2_3(acc, Xipjp, e1, acc);
            MUL2(tm, Ximjm, e2); SUB2(acc, acc, tm, NEG1);
            MUL2(tm, Xipjm, e3); SUB2(acc, acc, tm, NEG1);
            FMA2_3(acc, Ximjp, e4, acc);
            // laplacian = Ximj + Xijm - 4*Xc + Xijp + Xipjm + Xipj
            u64 lap; ADD2(lap, Ximj, Xijm);
            ADD2(lap, lap, Xijp);
            ADD2(lap, lap, Xipjm);
            ADD2(lap, lap, Xipj);
            FMA2_3(lap, Xc2, NFOUR, lap);
            // out = -(J1+J2+J3)*inv12 + mf*lap
            u64 res; MUL2(res, lap, MF2);
            FMA2_3(res, acc, NINV12, res);
            float rlo, rhi; UNPACK2(rlo, rhi, res);
            *(float2*)(o + i*64 + j) = make_float2(rlo, rhi);
        }
    }
}

extern "C" void kernel_launch(void* const* d_in, const int* in_sizes, int n_in,
                              void* d_out, int out_size) {
    // inputs (metadata order): t, y0, env, codes, params, domain
    const float* y0     = (const float*)d_in[1];
    const void*  envp   = d_in[2];
    const float* params = (const float*)d_in[4];
    const float* domain = (const float*)d_in[5];
    float* out = (float*)d_out;

    const int smemBytes = 17030 * (int)sizeof(float); // 68120 B
    cudaFuncSetAttribute(turb_kernel, cudaFuncAttributeMaxDynamicSharedMemorySize, smemBytes);

    init_tables_kernel<<<9, 256>>>();
    detect_env_kernel<<<8, 256>>>((const long long*)envp);
    turb_kernel<<<4096, NTHR, smemBytes>>>(y0, envp, params, domain, out);
}